// round 7
// baseline (speedup 1.0000x reference)
#include <cuda_runtime.h>
#include <cuda_bf16.h>
#include <cstdint>

// Problem constants
#define B_  4
#define T_  2048
#define D_  1024
#define H_  16
#define HD_ 64
#define M_  (B_ * T_)        // 8192

// Scratch (device globals — no allocation allowed)
__device__ __nv_bfloat16 g_qh[B_ * H_ * T_ * HD_];   // [B,H,T,HD] hi/lo
__device__ __nv_bfloat16 g_ql[B_ * H_ * T_ * HD_];
__device__ __nv_bfloat16 g_kh[B_ * H_ * T_ * HD_];
__device__ __nv_bfloat16 g_kl[B_ * H_ * T_ * HD_];
__device__ __nv_bfloat16 g_vh[B_ * H_ * T_ * HD_];
__device__ __nv_bfloat16 g_vl[B_ * H_ * T_ * HD_];
__device__ __nv_bfloat16 g_xhi[M_ * D_];        // x split       [M,K]
__device__ __nv_bfloat16 g_xlo[M_ * D_];
__device__ __nv_bfloat16 g_wqhi[D_ * 3 * D_];   // w_qkv split   [K,N]
__device__ __nv_bfloat16 g_wqlo[D_ * 3 * D_];
__device__ __nv_bfloat16 g_wphi[D_ * D_];       // w_proj split  [K,N]
__device__ __nv_bfloat16 g_wplo[D_ * D_];
__device__ __nv_bfloat16 g_ahi[M_ * D_];        // attention out [M,K]
__device__ __nv_bfloat16 g_alo[M_ * D_];

// ---------------------------------------------------------------------------
__device__ __forceinline__ uint32_t smem_u32(const void* p) {
    uint32_t a;
    asm("{ .reg .u64 t; cvta.to.shared.u64 t, %1; cvt.u32.u64 %0, t; }"
        : "=r"(a) : "l"(p));
    return a;
}

#define CP_ASYNC16(saddr, gaddr) \
    asm volatile("cp.async.cg.shared.global [%0], [%1], 16;" \
                 :: "r"(saddr), "l"(gaddr))
#define CP_COMMIT()  asm volatile("cp.async.commit_group;")
#define CP_WAIT1()   asm volatile("cp.async.wait_group 1;")
#define CP_WAIT0()   asm volatile("cp.async.wait_group 0;")

#define LDSM_X4(r0, r1, r2, r3, addr) \
    asm volatile("ldmatrix.sync.aligned.m8n8.x4.shared.b16 {%0,%1,%2,%3}, [%4];" \
                 : "=r"(r0), "=r"(r1), "=r"(r2), "=r"(r3) : "r"(addr))
#define LDSM_X4T(r0, r1, r2, r3, addr) \
    asm volatile("ldmatrix.sync.aligned.m8n8.x4.trans.shared.b16 {%0,%1,%2,%3}, [%4];" \
                 : "=r"(r0), "=r"(r1), "=r"(r2), "=r"(r3) : "r"(addr))

#define MMA_BF16(c, a, b0, b1) \
    asm volatile("mma.sync.aligned.m16n8k16.row.col.f32.bf16.bf16.f32 " \
        "{%0,%1,%2,%3}, {%4,%5,%6,%7}, {%8,%9}, {%0,%1,%2,%3};" \
        : "+f"((c)[0]), "+f"((c)[1]), "+f"((c)[2]), "+f"((c)[3]) \
        : "r"((a)[0]), "r"((a)[1]), "r"((a)[2]), "r"((a)[3]), "r"(b0), "r"(b1))

// pack two fp32 -> bf16x2 (lo in low half)
__device__ __forceinline__ uint32_t pack2bf(float lo, float hi) {
    uint32_t r;
    asm("cvt.rn.bf16x2.f32 %0, %1, %2;" : "=r"(r) : "f"(hi), "f"(lo));
    return r;
}
// residual pack: (lo,hi) - bf16(lo,hi)
__device__ __forceinline__ uint32_t resid2bf(uint32_t h, float lo, float hi) {
    float lf = __uint_as_float(h << 16);
    float hf = __uint_as_float(h & 0xffff0000u);
    return pack2bf(lo - lf, hi - hf);
}
__device__ __forceinline__ float ex2(float x) {
    float r;
    asm("ex2.approx.f32 %0, %1;" : "=f"(r) : "f"(x));
    return r;
}

// ---------------------------------------------------------------------------
// Prep: elementwise fp32 -> bf16 hi/lo split
// ---------------------------------------------------------------------------
__global__ void split_kernel(const float* __restrict__ src,
                             __nv_bfloat16* __restrict__ hi,
                             __nv_bfloat16* __restrict__ lo, int n)
{
    int i = (blockIdx.x * 256 + threadIdx.x) * 4;
    if (i >= n) return;
    float4 v = *(const float4*)(src + i);
    uint32_t h0 = pack2bf(v.x, v.y), h1 = pack2bf(v.z, v.w);
    uint32_t l0 = resid2bf(h0, v.x, v.y), l1 = resid2bf(h1, v.z, v.w);
    *(uint2*)(hi + i) = make_uint2(h0, h1);
    *(uint2*)(lo + i) = make_uint2(l0, l1);
}

// ---------------------------------------------------------------------------
// bf16x3 GEMM via mma.sync.  4 warps, 64x64 warp tiles on a 128x128 CTA tile:
// mma:ldsm ratio 6:1 (was 4:1) because ncu shows the L1/shared pipe (57.1%)
// co-saturated with tensor (59.6%) — LDSM traffic per FLOP is the binder.
// 3-stage cp.async pipeline, one __syncthreads per chunk (see R6 note).
// EPI=0: plain store.  EPI=1: QKV scatter into bf16 hi/lo q/k/v.
// ---------------------------------------------------------------------------
#define GEMM_SMEM (3 * 32768)

template <int EPI>
__global__ __launch_bounds__(128, 2) void gemm_bf16x3(
    const __nv_bfloat16* __restrict__ Ahi, const __nv_bfloat16* __restrict__ Alo,
    const __nv_bfloat16* __restrict__ Bhi, const __nv_bfloat16* __restrict__ Blo,
    const float* __restrict__ bias, float* __restrict__ C, int N)
{
    extern __shared__ char sm[];
    const uint32_t sb = smem_u32(sm);
    const int tid = threadIdx.x;
    const int warp = tid >> 5, lane = tid & 31;
    const int m0 = blockIdx.y * 128, n0 = blockIdx.x * 128;
    const int K = 1024;

    // producer: A row = tid (4 units of 16B), B row = tid>>2 (4 units)
    const int b_row = tid >> 2;
    const int b_cu0 = (tid & 3) * 4;

    auto load_stage = [&](int c, int buf) {
        const uint32_t st = sb + buf * 32768;
        #pragma unroll
        for (int part = 0; part < 2; part++) {
            const __nv_bfloat16* Ap = part ? Alo : Ahi;
            const __nv_bfloat16* Bp = part ? Blo : Bhi;
            const uint32_t ao = st + part * 8192;
            const uint32_t bo = st + 16384 + part * 8192;
            const __nv_bfloat16* ag = Ap + (long)(m0 + tid) * K + c * 32;
            const __nv_bfloat16* bg = Bp + (long)(c * 32 + b_row) * N + n0 + b_cu0 * 8;
            #pragma unroll
            for (int i = 0; i < 4; i++) {
                CP_ASYNC16(ao + tid * 64 + ((i ^ (tid & 3)) << 4), ag + i * 8);
                CP_ASYNC16(bo + b_row * 256 + (((b_cu0 + i) ^ (b_row & 7)) << 4),
                           bg + i * 8);
            }
        }
        CP_COMMIT();
    };

    const int wm = (warp & 1) * 64;
    const int wn = (warp >> 1) * 64;

    float acc[4][8][4] = {};

    const int a_lr = lane & 15;
    const int a_lk = lane >> 4;
    const int b_lk = lane & 15;
    const int b_ln = lane >> 4;
    const int nu0 = wn >> 3;

    load_stage(0, 0);
    load_stage(1, 1);

    int buf = 0;                 // c % 3
    for (int c = 0; c < 32; c++) {
        if (c < 31) CP_WAIT1(); else CP_WAIT0();
        __syncthreads();
        if (c + 2 < 32) {
            int nb = buf + 2; if (nb >= 3) nb -= 3;
            load_stage(c + 2, nb);
        }

        const uint32_t st = sb + buf * 32768;
        #pragma unroll
        for (int ks = 0; ks < 2; ks++) {
            uint32_t ah[4][4], al[4][4];
            #pragma unroll
            for (int mi = 0; mi < 4; mi++) {
                const int row = wm + mi * 16 + a_lr;
                const int ku = ks * 2 + a_lk;
                const uint32_t off = row * 64 + ((ku ^ (row & 3)) << 4);
                LDSM_X4(ah[mi][0], ah[mi][1], ah[mi][2], ah[mi][3], st + off);
                LDSM_X4(al[mi][0], al[mi][1], al[mi][2], al[mi][3], st + 8192 + off);
            }
            #pragma unroll
            for (int bi = 0; bi < 4; bi++) {
                const int krow = ks * 16 + b_lk;
                const int nu = nu0 + bi * 2 + b_ln;
                const uint32_t boff = krow * 256 + ((nu ^ (krow & 7)) << 4);
                uint32_t bh[4], bl[4];
                LDSM_X4T(bh[0], bh[1], bh[2], bh[3], st + 16384 + boff);
                LDSM_X4T(bl[0], bl[1], bl[2], bl[3], st + 24576 + boff);
                #pragma unroll
                for (int mi = 0; mi < 4; mi++) {
                    MMA_BF16(acc[mi][bi * 2],     ah[mi], bh[0], bh[1]);
                    MMA_BF16(acc[mi][bi * 2],     ah[mi], bl[0], bl[1]);
                    MMA_BF16(acc[mi][bi * 2],     al[mi], bh[0], bh[1]);
                    MMA_BF16(acc[mi][bi * 2 + 1], ah[mi], bh[2], bh[3]);
                    MMA_BF16(acc[mi][bi * 2 + 1], ah[mi], bl[2], bl[3]);
                    MMA_BF16(acc[mi][bi * 2 + 1], al[mi], bh[2], bh[3]);
                }
            }
        }
        if (++buf == 3) buf = 0;
    }

    // Epilogue
    const int tg = lane >> 2, ti = lane & 3;
    #pragma unroll
    for (int mi = 0; mi < 4; mi++) {
        #pragma unroll
        for (int nj = 0; nj < 8; nj++) {
            const int n = n0 + wn + nj * 8 + ti * 2;
            const float bx = __ldg(&bias[n]), by = __ldg(&bias[n + 1]);
            #pragma unroll
            for (int half = 0; half < 2; half++) {
                const int m = m0 + wm + mi * 16 + tg + half * 8;
                float ox = acc[mi][nj][half * 2 + 0] + bx;
                float oy = acc[mi][nj][half * 2 + 1] + by;
                if (EPI == 0) {
                    *(float2*)(C + (long)m * N + n) = make_float2(ox, oy);
                } else {
                    const int bidx = m >> 11, t = m & (T_ - 1);
                    const int which = n >> 10;
                    const int rem = n & 1023;
                    const int h = rem >> 6, hd = rem & 63;
                    __nv_bfloat16* dh = (which == 0) ? g_qh : ((which == 1) ? g_kh : g_vh);
                    __nv_bfloat16* dl = (which == 0) ? g_ql : ((which == 1) ? g_kl : g_vl);
                    long off = (((long)bidx * H_ + h) * T_ + t) * HD_ + hd;
                    uint32_t hp = pack2bf(ox, oy);
                    *(uint32_t*)(dh + off) = hp;
                    *(uint32_t*)(dl + off) = resid2bf(hp, ox, oy);
                }
            }
        }
    }
}

// ---------------------------------------------------------------------------
// Tensor-core causal flash attention (bf16x3), FA2 register softmax.
// CTA: 128 q-rows, 8 warps x m16.  kv tiles of 64, cp.async double buffer.
// smem: Qh/Ql 32KB + 2 stages x (Kh,Kl,Vh,Vl 8KB each) = 96KB.
// ---------------------------------------------------------------------------
#define ATTN_SMEM (32768 + 2 * 32768)
#define SCL2 0.1803368801111204f   // 0.125 * log2(e)

__global__ __launch_bounds__(256, 1) void attn_tc_kernel()
{
    extern __shared__ char sm[];
    const uint32_t sb = smem_u32(sm);
    const int tid = threadIdx.x;
    const int w = tid >> 5, lane = tid & 31;
    const int tg = lane >> 2, ti = lane & 3;
    const int qt = 15 - blockIdx.x;           // big tiles first
    const int bh = blockIdx.y;
    const int qbase = qt * 128 + w * 16;
    const int r0 = qbase + tg;                // thread rows r0, r0+8

    const long bhoff = (long)bh * T_ * HD_;

    // ---- issue Q loads (rows of 128B, swizzled) + KV tile 0
    {
        const int row = tid >> 1;
        const int u0 = (tid & 1) * 4;
        const long gq = bhoff + (long)(qt * 128 + row) * HD_;
        #pragma unroll
        for (int i = 0; i < 4; i++) {
            const int u = u0 + i;
            const uint32_t so = row * 128 + ((u ^ (row & 7)) << 4);
            CP_ASYNC16(sb + so,         g_qh + gq + u * 8);
            CP_ASYNC16(sb + 16384 + so, g_ql + gq + u * 8);
        }
    }
    const int kvp = tid >> 6;        // 0..3 -> Kh,Kl,Vh,Vl
    const int kvr = tid & 63;        // row within tile
    const __nv_bfloat16* kvsrc =
        (kvp == 0) ? g_kh : (kvp == 1) ? g_kl : (kvp == 2) ? g_vh : g_vl;
    const uint32_t kvdst_off = kvp * 8192 + kvr * 128;

    auto load_kv = [&](int kb, int buf) {
        const uint32_t st = sb + 32768 + buf * 32768;
        const long gs = bhoff + (long)(kb * 64 + kvr) * HD_;
        #pragma unroll
        for (int u = 0; u < 8; u++)
            CP_ASYNC16(st + kvdst_off + ((u ^ (kvr & 7)) << 4), kvsrc + gs + u * 8);
    };
    load_kv(0, 0);
    CP_COMMIT();
    CP_WAIT0();
    __syncthreads();

    // ---- Q fragments (A-frags, m16k16 per hd-step)
    uint32_t qh[4][4], ql[4][4];
    #pragma unroll
    for (int s = 0; s < 4; s++) {
        const int row = w * 16 + (lane & 15);
        const int ku = s * 2 + (lane >> 4);
        const uint32_t ad = sb + row * 128 + ((ku ^ (row & 7)) << 4);
        LDSM_X4(qh[s][0], qh[s][1], qh[s][2], qh[s][3], ad);
        LDSM_X4(ql[s][0], ql[s][1], ql[s][2], ql[s][3], ad + 16384);
    }

    float oacc[8][4] = {};
    float m2a = -1e30f, m2b = -1e30f;
    float la = 0.f, lb = 0.f;

    const int nt = 2 * qt + 2;
    for (int kb = 0; kb < nt; kb++) {
        if (kb > 0) CP_WAIT0();
        __syncthreads();
        if (kb + 1 < nt) { load_kv(kb + 1, (kb + 1) & 1); CP_COMMIT(); }

        if (kb * 64 > qbase + 15) continue;   // warp fully masked

        const uint32_t stK = sb + 32768 + (kb & 1) * 32768;
        const uint32_t stV = stK + 16384;

        // ---- S = Q K^T (bf16x3)
        float sacc[8][4] = {};
        #pragma unroll
        for (int s = 0; s < 4; s++) {
            #pragma unroll
            for (int g = 0; g < 4; g++) {
                const int row = g * 16 + (lane & 15);
                const uint32_t ka = stK + row * 128 +
                    (((s * 2 + (lane >> 4)) ^ (row & 7)) << 4);
                uint32_t h0, h1, h2, h3, l0, l1, l2, l3;
                LDSM_X4(h0, h1, h2, h3, ka);
                LDSM_X4(l0, l1, l2, l3, ka + 8192);
                MMA_BF16(sacc[2 * g],     qh[s], h0, h2);
                MMA_BF16(sacc[2 * g],     ql[s], h0, h2);
                MMA_BF16(sacc[2 * g],     qh[s], l0, l2);
                MMA_BF16(sacc[2 * g + 1], qh[s], h1, h3);
                MMA_BF16(sacc[2 * g + 1], ql[s], h1, h3);
                MMA_BF16(sacc[2 * g + 1], qh[s], l1, l3);
            }
        }

        // ---- scale to log2-domain + causal mask + row max
        const bool needmask = (kb * 64 + 63) > r0;
        float mra = -1e30f, mrb = -1e30f;
        #pragma unroll
        for (int j = 0; j < 8; j++) {
            const int c0 = kb * 64 + 8 * j + 2 * ti, c1 = c0 + 1;
            float z0 = sacc[j][0] * SCL2;
            float z1 = sacc[j][1] * SCL2;
            float z2 = sacc[j][2] * SCL2;
            float z3 = sacc[j][3] * SCL2;
            if (needmask) {
                if (c0 > r0) z0 = -1e30f;
                if (c1 > r0) z1 = -1e30f;
                if (c0 > r0 + 8) z2 = -1e30f;
                if (c1 > r0 + 8) z3 = -1e30f;
            }
            sacc[j][0] = z0; sacc[j][1] = z1; sacc[j][2] = z2; sacc[j][3] = z3;
            mra = fmaxf(mra, fmaxf(z0, z1));
            mrb = fmaxf(mrb, fmaxf(z2, z3));
        }
        mra = fmaxf(mra, __shfl_xor_sync(0xffffffffu, mra, 1));
        mra = fmaxf(mra, __shfl_xor_sync(0xffffffffu, mra, 2));
        mrb = fmaxf(mrb, __shfl_xor_sync(0xffffffffu, mrb, 1));
        mrb = fmaxf(mrb, __shfl_xor_sync(0xffffffffu, mrb, 2));

        const float mna = fmaxf(m2a, mra);
        const float mnb = fmaxf(m2b, mrb);
        const float alpa = ex2(m2a - mna);
        const float alpb = ex2(m2b - mnb);
        m2a = mna; m2b = mnb;

        #pragma unroll
        for (int j = 0; j < 8; j++) {
            oacc[j][0] *= alpa; oacc[j][1] *= alpa;
            oacc[j][2] *= alpb; oacc[j][3] *= alpb;
        }

        // ---- exp + pack P hi/lo (A-frag layout!)
        uint32_t pha[8], phb[8], pla[8], plb[8];
        float sa = 0.f, sbm = 0.f;
        #pragma unroll
        for (int j = 0; j < 8; j++) {
            float p0 = ex2(sacc[j][0] - m2a);
            float p1 = ex2(sacc[j][1] - m2a);
            float p2 = ex2(sacc[j][2] - m2b);
            float p3 = ex2(sacc[j][3] - m2b);
            sa += p0 + p1; sbm += p2 + p3;
            pha[j] = pack2bf(p0, p1); pla[j] = resid2bf(pha[j], p0, p1);
            phb[j] = pack2bf(p2, p3); plb[j] = resid2bf(phb[j], p2, p3);
        }
        sa  += __shfl_xor_sync(0xffffffffu, sa, 1);
        sa  += __shfl_xor_sync(0xffffffffu, sa, 2);
        sbm += __shfl_xor_sync(0xffffffffu, sbm, 1);
        sbm += __shfl_xor_sync(0xffffffffu, sbm, 2);
        la = la * alpa + sa;
        lb = lb * alpb + sbm;

        // ---- O += P V (bf16x3)
        #pragma unroll
        for (int s = 0; s < 4; s++) {
            uint32_t aH[4] = {pha[2 * s], phb[2 * s], pha[2 * s + 1], phb[2 * s + 1]};
            uint32_t aL[4] = {pla[2 * s], plb[2 * s], pla[2 * s + 1], plb[2 * s + 1]};
            #pragma unroll
            for (int b = 0; b < 4; b++) {
                const int krow = s * 16 + (lane & 15);
                const uint32_t va = stV + krow * 128 +
                    (((b * 2 + (lane >> 4)) ^ (krow & 7)) << 4);
                uint32_t h0, h1, h2, h3, l0, l1, l2, l3;
                LDSM_X4T(h0, h1, h2, h3, va);
                MMA_BF16(oacc[2 * b],     aH, h0, h1);
                MMA_BF16(oacc[2 * b],     aL, h0, h1);
                MMA_BF16(oacc[2 * b + 1], aH, h2, h3);
                MMA_BF16(oacc[2 * b + 1], aL, h2, h3);
                LDSM_X4T(l0, l1, l2, l3, va + 8192);
                MMA_BF16(oacc[2 * b],     aH, l0, l1);
                MMA_BF16(oacc[2 * b + 1], aH, l2, l3);
            }
        }
    }

    // ---- epilogue: normalize, bf16 hi/lo split, write [B,T,H*HD]
    const float inva = 1.0f / la, invb = 1.0f / lb;
    const int bidx = bh >> 4, h = bh & 15;
    const long rowa = ((long)(bidx * T_ + qbase + tg)) * D_ + h * HD_;
    const long rowb = rowa + 8L * D_;
    #pragma unroll
    for (int j = 0; j < 8; j++) {
        const int col = 8 * j + 2 * ti;
        float f0 = oacc[j][0] * inva, f1 = oacc[j][1] * inva;
        float f2 = oacc[j][2] * invb, f3 = oacc[j][3] * invb;
        uint32_t hpa = pack2bf(f0, f1);
        uint32_t hpb = pack2bf(f2, f3);
        *(uint32_t*)(g_ahi + rowa + col) = hpa;
        *(uint32_t*)(g_alo + rowa + col) = resid2bf(hpa, f0, f1);
        *(uint32_t*)(g_ahi + rowb + col) = hpb;
        *(uint32_t*)(g_alo + rowb + col) = resid2bf(hpb, f2, f3);
    }
}

// ---------------------------------------------------------------------------
extern "C" void kernel_launch(void* const* d_in, const int* in_sizes, int n_in,
                              void* d_out, int out_size)
{
    const float* x      = (const float*)d_in[0];
    const float* w_qkv  = (const float*)d_in[1];
    const float* b_qkv  = (const float*)d_in[2];
    const float* w_proj = (const float*)d_in[3];
    const float* b_proj = (const float*)d_in[4];
    float* out = (float*)d_out;

    __nv_bfloat16 *xhi, *xlo, *wqhi, *wqlo, *wphi, *wplo, *ahi, *alo;
    cudaGetSymbolAddress((void**)&xhi,  g_xhi);
    cudaGetSymbolAddress((void**)&xlo,  g_xlo);
    cudaGetSymbolAddress((void**)&wqhi, g_wqhi);
    cudaGetSymbolAddress((void**)&wqlo, g_wqlo);
    cudaGetSymbolAddress((void**)&wphi, g_wphi);
    cudaGetSymbolAddress((void**)&wplo, g_wplo);
    cudaGetSymbolAddress((void**)&ahi,  g_ahi);
    cudaGetSymbolAddress((void**)&alo,  g_alo);

    // 0) bf16 hi/lo splits
    split_kernel<<<(M_ * D_) / 1024, 256>>>(x, xhi, xlo, M_ * D_);
    split_kernel<<<(D_ * 3 * D_) / 1024, 256>>>(w_qkv, wqhi, wqlo, D_ * 3 * D_);
    split_kernel<<<(D_ * D_) / 1024, 256>>>(w_proj, wphi, wplo, D_ * D_);

    // 1) QKV GEMM (bf16x3) -> q/k/v bf16 hi/lo
    cudaFuncSetAttribute((const void*)gemm_bf16x3<1>,
                         cudaFuncAttributeMaxDynamicSharedMemorySize, GEMM_SMEM);
    gemm_bf16x3<1><<<dim3(3 * D_ / 128, M_ / 128), 128, GEMM_SMEM>>>(
        xhi, xlo, wqhi, wqlo, b_qkv, nullptr, 3 * D_);

    // 2) tensor-core flash attention
    cudaFuncSetAttribute((const void*)attn_tc_kernel,
                         cudaFuncAttributeMaxDynamicSharedMemorySize, ATTN_SMEM);
    attn_tc_kernel<<<dim3(T_ / 128, B_ * H_), 256, ATTN_SMEM>>>();

    // 3) proj GEMM (bf16x3)
    cudaFuncSetAttribute((const void*)gemm_bf16x3<0>,
                         cudaFuncAttributeMaxDynamicSharedMemorySize, GEMM_SMEM);
    gemm_bf16x3<0><<<dim3(D_ / 128, M_ / 128), 128, GEMM_SMEM>>>(
        ahi, alo, wphi, wplo, b_proj, out, D_);
}

// round 8
// speedup vs baseline: 1.1937x; 1.1937x over previous
#include <cuda_runtime.h>
#include <cuda_bf16.h>
#include <cuda_fp16.h>
#include <cstdint>

// Problem constants
#define B_  4
#define T_  2048
#define D_  1024
#define H_  16
#define HD_ 64
#define M_  (B_ * T_)        // 8192

// Scratch (device globals — no allocation allowed)
__device__ __nv_bfloat16 g_qh[B_ * H_ * T_ * HD_];   // q (pre-scaled) bf16 hi/lo
__device__ __nv_bfloat16 g_ql[B_ * H_ * T_ * HD_];
__device__ __nv_bfloat16 g_kh[B_ * H_ * T_ * HD_];   // k bf16 hi/lo
__device__ __nv_bfloat16 g_kl[B_ * H_ * T_ * HD_];
__device__ __half        g_vh[B_ * H_ * T_ * HD_];   // v fp16 hi/lo
__device__ __half        g_vl[B_ * H_ * T_ * HD_];
__device__ __nv_bfloat16 g_xhi[M_ * D_];        // x split       [M,K]
__device__ __nv_bfloat16 g_xlo[M_ * D_];
__device__ __nv_bfloat16 g_wqhi[D_ * 3 * D_];   // w_qkv split   [K,N]
__device__ __nv_bfloat16 g_wqlo[D_ * 3 * D_];
__device__ __nv_bfloat16 g_wphi[D_ * D_];       // w_proj split  [K,N]
__device__ __nv_bfloat16 g_wplo[D_ * D_];
__device__ __nv_bfloat16 g_ahi[M_ * D_];        // attention out [M,K]
__device__ __nv_bfloat16 g_alo[M_ * D_];

// ---------------------------------------------------------------------------
__device__ __forceinline__ uint32_t smem_u32(const void* p) {
    uint32_t a;
    asm("{ .reg .u64 t; cvta.to.shared.u64 t, %1; cvt.u32.u64 %0, t; }"
        : "=r"(a) : "l"(p));
    return a;
}

#define CP_ASYNC16(saddr, gaddr) \
    asm volatile("cp.async.cg.shared.global [%0], [%1], 16;" \
                 :: "r"(saddr), "l"(gaddr))
#define CP_COMMIT()  asm volatile("cp.async.commit_group;")
#define CP_WAIT1()   asm volatile("cp.async.wait_group 1;")
#define CP_WAIT0()   asm volatile("cp.async.wait_group 0;")

#define LDSM_X4(r0, r1, r2, r3, addr) \
    asm volatile("ldmatrix.sync.aligned.m8n8.x4.shared.b16 {%0,%1,%2,%3}, [%4];" \
                 : "=r"(r0), "=r"(r1), "=r"(r2), "=r"(r3) : "r"(addr))
#define LDSM_X4T(r0, r1, r2, r3, addr) \
    asm volatile("ldmatrix.sync.aligned.m8n8.x4.trans.shared.b16 {%0,%1,%2,%3}, [%4];" \
                 : "=r"(r0), "=r"(r1), "=r"(r2), "=r"(r3) : "r"(addr))

#define MMA_BF16(c, a, b0, b1) \
    asm volatile("mma.sync.aligned.m16n8k16.row.col.f32.bf16.bf16.f32 " \
        "{%0,%1,%2,%3}, {%4,%5,%6,%7}, {%8,%9}, {%0,%1,%2,%3};" \
        : "+f"((c)[0]), "+f"((c)[1]), "+f"((c)[2]), "+f"((c)[3]) \
        : "r"((a)[0]), "r"((a)[1]), "r"((a)[2]), "r"((a)[3]), "r"(b0), "r"(b1))

#define MMA_F16(c, a, b0, b1) \
    asm volatile("mma.sync.aligned.m16n8k16.row.col.f32.f16.f16.f32 " \
        "{%0,%1,%2,%3}, {%4,%5,%6,%7}, {%8,%9}, {%0,%1,%2,%3};" \
        : "+f"((c)[0]), "+f"((c)[1]), "+f"((c)[2]), "+f"((c)[3]) \
        : "r"((a)[0]), "r"((a)[1]), "r"((a)[2]), "r"((a)[3]), "r"(b0), "r"(b1))

// pack two fp32 -> bf16x2 (lo in low half)
__device__ __forceinline__ uint32_t pack2bf(float lo, float hi) {
    uint32_t r;
    asm("cvt.rn.bf16x2.f32 %0, %1, %2;" : "=r"(r) : "f"(hi), "f"(lo));
    return r;
}
// residual pack: (lo,hi) - bf16(lo,hi)
__device__ __forceinline__ uint32_t resid2bf(uint32_t h, float lo, float hi) {
    float lf = __uint_as_float(h << 16);
    float hf = __uint_as_float(h & 0xffff0000u);
    return pack2bf(lo - lf, hi - hf);
}
// pack two fp32 -> fp16x2 (lo in low half)
__device__ __forceinline__ uint32_t pack2hf(float lo, float hi) {
    uint32_t r;
    asm("cvt.rn.f16x2.f32 %0, %1, %2;" : "=r"(r) : "f"(hi), "f"(lo));
    return r;
}
__device__ __forceinline__ uint32_t resid2hf(uint32_t h, float lo, float hi) {
    __half2 hh = *reinterpret_cast<__half2*>(&h);
    return pack2hf(lo - __half2float(hh.x), hi - __half2float(hh.y));
}
__device__ __forceinline__ float ex2(float x) {
    float r;
    asm("ex2.approx.f32 %0, %1;" : "=f"(r) : "f"(x));
    return r;
}

// ---------------------------------------------------------------------------
// Prep: elementwise fp32 -> bf16 hi/lo split
// ---------------------------------------------------------------------------
__global__ void split_kernel(const float* __restrict__ src,
                             __nv_bfloat16* __restrict__ hi,
                             __nv_bfloat16* __restrict__ lo, int n)
{
    int i = (blockIdx.x * 256 + threadIdx.x) * 4;
    if (i >= n) return;
    float4 v = *(const float4*)(src + i);
    uint32_t h0 = pack2bf(v.x, v.y), h1 = pack2bf(v.z, v.w);
    uint32_t l0 = resid2bf(h0, v.x, v.y), l1 = resid2bf(h1, v.z, v.w);
    *(uint2*)(hi + i) = make_uint2(h0, h1);
    *(uint2*)(lo + i) = make_uint2(l0, l1);
}

// ---------------------------------------------------------------------------
// bf16x3 GEMM via mma.sync — R6 configuration (16 warps/SM is the proven
// optimum; R4/R7 showed 8 warps/SM caps tensor at ~48%).
// 8 warps, 64x32 warp tiles, 3-stage cp.async pipeline, 1 sync/chunk.
// EPI=0: plain store.  EPI=1: QKV scatter (q pre-scaled by SCL2, bf16 hi/lo;
// k bf16 hi/lo; v fp16 hi/lo).
// ---------------------------------------------------------------------------
#define GEMM_SMEM (3 * 32768)
#define SCL2 0.1803368801111204f   // 0.125 * log2(e)

template <int EPI>
__global__ __launch_bounds__(256, 2) void gemm_bf16x3(
    const __nv_bfloat16* __restrict__ Ahi, const __nv_bfloat16* __restrict__ Alo,
    const __nv_bfloat16* __restrict__ Bhi, const __nv_bfloat16* __restrict__ Blo,
    const float* __restrict__ bias, float* __restrict__ C, int N)
{
    extern __shared__ char sm[];
    const uint32_t sb = smem_u32(sm);
    const int tid = threadIdx.x;
    const int warp = tid >> 5, lane = tid & 31;
    const int m0 = blockIdx.y * 128, n0 = blockIdx.x * 128;
    const int K = 1024;

    const int a_r0 = (tid * 2) >> 2,     a_c0 = (tid * 2) & 3;
    const int a_r1 = (tid * 2 + 1) >> 2, a_c1 = (tid * 2 + 1) & 3;
    const int b_r0 = (tid * 2) >> 4,     b_c0 = (tid * 2) & 15;
    const int b_r1 = (tid * 2 + 1) >> 4, b_c1 = (tid * 2 + 1) & 15;

    auto load_stage = [&](int c, int buf) {
        const uint32_t st = sb + buf * 32768;
        #pragma unroll
        for (int part = 0; part < 2; part++) {
            const __nv_bfloat16* Ap = part ? Alo : Ahi;
            const __nv_bfloat16* Bp = part ? Blo : Bhi;
            const uint32_t ao = st + part * 8192;
            const uint32_t bo = st + 16384 + part * 8192;
            CP_ASYNC16(ao + a_r0 * 64 + ((a_c0 ^ (a_r0 & 3)) << 4),
                       Ap + (long)(m0 + a_r0) * K + c * 32 + a_c0 * 8);
            CP_ASYNC16(ao + a_r1 * 64 + ((a_c1 ^ (a_r1 & 3)) << 4),
                       Ap + (long)(m0 + a_r1) * K + c * 32 + a_c1 * 8);
            CP_ASYNC16(bo + b_r0 * 256 + ((b_c0 ^ (b_r0 & 7)) << 4),
                       Bp + (long)(c * 32 + b_r0) * N + n0 + b_c0 * 8);
            CP_ASYNC16(bo + b_r1 * 256 + ((b_c1 ^ (b_r1 & 7)) << 4),
                       Bp + (long)(c * 32 + b_r1) * N + n0 + b_c1 * 8);
        }
        CP_COMMIT();
    };

    const int wm = (warp & 1) * 64;
    const int wn = (warp >> 1) * 32;

    float acc[4][4][4] = {};

    const int a_lr = lane & 15;
    const int a_lk = lane >> 4;
    const int b_lk = lane & 15;
    const int b_ln = lane >> 4;
    const int nu0 = wn >> 3;

    load_stage(0, 0);
    load_stage(1, 1);

    int buf = 0;                 // c % 3
    for (int c = 0; c < 32; c++) {
        if (c < 31) CP_WAIT1(); else CP_WAIT0();
        __syncthreads();
        if (c + 2 < 32) {
            int nb = buf + 2; if (nb >= 3) nb -= 3;
            load_stage(c + 2, nb);
        }

        const uint32_t st = sb + buf * 32768;
        #pragma unroll
        for (int ks = 0; ks < 2; ks++) {
            uint32_t ah[4][4], al[4][4];
            #pragma unroll
            for (int mi = 0; mi < 4; mi++) {
                const int row = wm + mi * 16 + a_lr;
                const int ku = ks * 2 + a_lk;
                const uint32_t off = row * 64 + ((ku ^ (row & 3)) << 4);
                LDSM_X4(ah[mi][0], ah[mi][1], ah[mi][2], ah[mi][3], st + off);
                LDSM_X4(al[mi][0], al[mi][1], al[mi][2], al[mi][3], st + 8192 + off);
            }
            #pragma unroll
            for (int bi = 0; bi < 2; bi++) {
                const int krow = ks * 16 + b_lk;
                const int nu = nu0 + bi * 2 + b_ln;
                const uint32_t boff = krow * 256 + ((nu ^ (krow & 7)) << 4);
                uint32_t bh[4], bl[4];
                LDSM_X4T(bh[0], bh[1], bh[2], bh[3], st + 16384 + boff);
                LDSM_X4T(bl[0], bl[1], bl[2], bl[3], st + 24576 + boff);
                #pragma unroll
                for (int mi = 0; mi < 4; mi++) {
                    MMA_BF16(acc[mi][bi * 2],     ah[mi], bh[0], bh[1]);
                    MMA_BF16(acc[mi][bi * 2],     ah[mi], bl[0], bl[1]);
                    MMA_BF16(acc[mi][bi * 2],     al[mi], bh[0], bh[1]);
                    MMA_BF16(acc[mi][bi * 2 + 1], ah[mi], bh[2], bh[3]);
                    MMA_BF16(acc[mi][bi * 2 + 1], ah[mi], bl[2], bl[3]);
                    MMA_BF16(acc[mi][bi * 2 + 1], al[mi], bh[2], bh[3]);
                }
            }
        }
        if (++buf == 3) buf = 0;
    }

    // Epilogue
    const int tg = lane >> 2, ti = lane & 3;
    #pragma unroll
    for (int mi = 0; mi < 4; mi++) {
        #pragma unroll
        for (int nj = 0; nj < 4; nj++) {
            const int n = n0 + wn + nj * 8 + ti * 2;
            const float bx = __ldg(&bias[n]), by = __ldg(&bias[n + 1]);
            #pragma unroll
            for (int half = 0; half < 2; half++) {
                const int m = m0 + wm + mi * 16 + tg + half * 8;
                float ox = acc[mi][nj][half * 2 + 0] + bx;
                float oy = acc[mi][nj][half * 2 + 1] + by;
                if (EPI == 0) {
                    *(float2*)(C + (long)m * N + n) = make_float2(ox, oy);
                } else {
                    const int bidx = m >> 11, t = m & (T_ - 1);
                    const int which = n >> 10;
                    const int rem = n & 1023;
                    const int h = rem >> 6, hd = rem & 63;
                    long off = (((long)bidx * H_ + h) * T_ + t) * HD_ + hd;
                    if (which == 0) {
                        ox *= SCL2; oy *= SCL2;      // pre-scale q
                        uint32_t hp = pack2bf(ox, oy);
                        *(uint32_t*)(g_qh + off) = hp;
                        *(uint32_t*)(g_ql + off) = resid2bf(hp, ox, oy);
                    } else if (which == 1) {
                        uint32_t hp = pack2bf(ox, oy);
                        *(uint32_t*)(g_kh + off) = hp;
                        *(uint32_t*)(g_kl + off) = resid2bf(hp, ox, oy);
                    } else {
                        uint32_t hp = pack2hf(ox, oy);
                        *(uint32_t*)(g_vh + off) = hp;
                        *(uint32_t*)(g_vl + off) = resid2hf(hp, ox, oy);
                    }
                }
            }
        }
    }
}

// ---------------------------------------------------------------------------
// Tensor-core causal flash attention.
// S = QK^T in bf16x3 (q pre-scaled to log2 domain).  PV in fp16x2:
// P packed to a SINGLE fp16, V stored fp16 hi/lo  ->  64 PV mma/chunk (was 96)
// and no P-residual packing.  Error ~2.8e-4 relative, gate is 1e-3.
// ---------------------------------------------------------------------------
#define ATTN_SMEM (32768 + 2 * 32768)

__global__ __launch_bounds__(256, 1) void attn_tc_kernel()
{
    extern __shared__ char sm[];
    const uint32_t sb = smem_u32(sm);
    const int tid = threadIdx.x;
    const int w = tid >> 5, lane = tid & 31;
    const int tg = lane >> 2, ti = lane & 3;
    const int qt = 15 - blockIdx.x;           // big tiles first
    const int bh = blockIdx.y;
    const int qbase = qt * 128 + w * 16;
    const int r0 = qbase + tg;                // thread rows r0, r0+8

    const long bhoff = (long)bh * T_ * HD_;

    // ---- issue Q loads (rows of 128B, swizzled) + KV tile 0
    {
        const int row = tid >> 1;
        const int u0 = (tid & 1) * 4;
        const long gq = bhoff + (long)(qt * 128 + row) * HD_;
        #pragma unroll
        for (int i = 0; i < 4; i++) {
            const int u = u0 + i;
            const uint32_t so = row * 128 + ((u ^ (row & 7)) << 4);
            CP_ASYNC16(sb + so,         g_qh + gq + u * 8);
            CP_ASYNC16(sb + 16384 + so, g_ql + gq + u * 8);
        }
    }
    const int kvp = tid >> 6;        // 0..3 -> Kh,Kl,Vh,Vl
    const int kvr = tid & 63;        // row within tile
    const char* kvsrc =
        (kvp == 0) ? (const char*)g_kh : (kvp == 1) ? (const char*)g_kl :
        (kvp == 2) ? (const char*)g_vh : (const char*)g_vl;
    const uint32_t kvdst_off = kvp * 8192 + kvr * 128;

    auto load_kv = [&](int kb, int buf) {
        const uint32_t st = sb + 32768 + buf * 32768;
        const long gs = (bhoff + (long)(kb * 64 + kvr) * HD_) * 2;  // bytes
        #pragma unroll
        for (int u = 0; u < 8; u++)
            CP_ASYNC16(st + kvdst_off + ((u ^ (kvr & 7)) << 4),
                       kvsrc + gs + u * 16);
    };
    load_kv(0, 0);
    CP_COMMIT();
    CP_WAIT0();
    __syncthreads();

    // ---- Q fragments (A-frags, m16k16 per hd-step)
    uint32_t qh[4][4], ql[4][4];
    #pragma unroll
    for (int s = 0; s < 4; s++) {
        const int row = w * 16 + (lane & 15);
        const int ku = s * 2 + (lane >> 4);
        const uint32_t ad = sb + row * 128 + ((ku ^ (row & 7)) << 4);
        LDSM_X4(qh[s][0], qh[s][1], qh[s][2], qh[s][3], ad);
        LDSM_X4(ql[s][0], ql[s][1], ql[s][2], ql[s][3], ad + 16384);
    }

    float oacc[8][4] = {};
    float m2a = -1e30f, m2b = -1e30f;
    float la = 0.f, lb = 0.f;

    const int nt = 2 * qt + 2;
    for (int kb = 0; kb < nt; kb++) {
        if (kb > 0) CP_WAIT0();
        __syncthreads();
        if (kb + 1 < nt) { load_kv(kb + 1, (kb + 1) & 1); CP_COMMIT(); }

        if (kb * 64 > qbase + 15) continue;   // warp fully masked

        const uint32_t stK = sb + 32768 + (kb & 1) * 32768;
        const uint32_t stV = stK + 16384;

        // ---- S = Q K^T (bf16x3, already log2-scaled via q)
        float sacc[8][4] = {};
        #pragma unroll
        for (int s = 0; s < 4; s++) {
            #pragma unroll
            for (int g = 0; g < 4; g++) {
                const int row = g * 16 + (lane & 15);
                const uint32_t ka = stK + row * 128 +
                    (((s * 2 + (lane >> 4)) ^ (row & 7)) << 4);
                uint32_t h0, h1, h2, h3, l0, l1, l2, l3;
                LDSM_X4(h0, h1, h2, h3, ka);
                LDSM_X4(l0, l1, l2, l3, ka + 8192);
                MMA_BF16(sacc[2 * g],     qh[s], h0, h2);
                MMA_BF16(sacc[2 * g],     ql[s], h0, h2);
                MMA_BF16(sacc[2 * g],     qh[s], l0, l2);
                MMA_BF16(sacc[2 * g + 1], qh[s], h1, h3);
                MMA_BF16(sacc[2 * g + 1], ql[s], h1, h3);
                MMA_BF16(sacc[2 * g + 1], qh[s], l1, l3);
            }
        }

        // ---- causal mask + row max (values already in log2 domain)
        const bool needmask = (kb * 64 + 63) > r0;
        float mra = -1e30f, mrb = -1e30f;
        #pragma unroll
        for (int j = 0; j < 8; j++) {
            const int c0 = kb * 64 + 8 * j + 2 * ti, c1 = c0 + 1;
            float z0 = sacc[j][0];
            float z1 = sacc[j][1];
            float z2 = sacc[j][2];
            float z3 = sacc[j][3];
            if (needmask) {
                if (c0 > r0) z0 = -1e30f;
                if (c1 > r0) z1 = -1e30f;
                if (c0 > r0 + 8) z2 = -1e30f;
                if (c1 > r0 + 8) z3 = -1e30f;
            }
            sacc[j][0] = z0; sacc[j][1] = z1; sacc[j][2] = z2; sacc[j][3] = z3;
            mra = fmaxf(mra, fmaxf(z0, z1));
            mrb = fmaxf(mrb, fmaxf(z2, z3));
        }
        mra = fmaxf(mra, __shfl_xor_sync(0xffffffffu, mra, 1));
        mra = fmaxf(mra, __shfl_xor_sync(0xffffffffu, mra, 2));
        mrb = fmaxf(mrb, __shfl_xor_sync(0xffffffffu, mrb, 1));
        mrb = fmaxf(mrb, __shfl_xor_sync(0xffffffffu, mrb, 2));

        const float mna = fmaxf(m2a, mra);
        const float mnb = fmaxf(m2b, mrb);
        const float alpa = ex2(m2a - mna);
        const float alpb = ex2(m2b - mnb);
        m2a = mna; m2b = mnb;

        #pragma unroll
        for (int j = 0; j < 8; j++) {
            oacc[j][0] *= alpa; oacc[j][1] *= alpa;
            oacc[j][2] *= alpb; oacc[j][3] *= alpb;
        }

        // ---- exp + pack P to single fp16 (A-frag layout)
        uint32_t pha[8], phb[8];
        float sa = 0.f, sbm = 0.f;
        #pragma unroll
        for (int j = 0; j < 8; j++) {
            float p0 = ex2(sacc[j][0] - m2a);
            float p1 = ex2(sacc[j][1] - m2a);
            float p2 = ex2(sacc[j][2] - m2b);
            float p3 = ex2(sacc[j][3] - m2b);
            sa += p0 + p1; sbm += p2 + p3;
            pha[j] = pack2hf(p0, p1);
            phb[j] = pack2hf(p2, p3);
        }
        sa  += __shfl_xor_sync(0xffffffffu, sa, 1);
        sa  += __shfl_xor_sync(0xffffffffu, sa, 2);
        sbm += __shfl_xor_sync(0xffffffffu, sbm, 1);
        sbm += __shfl_xor_sync(0xffffffffu, sbm, 2);
        la = la * alpa + sa;
        lb = lb * alpb + sbm;

        // ---- O += P V (fp16x2: P_fp16 * (Vh + Vl))
        #pragma unroll
        for (int s = 0; s < 4; s++) {
            uint32_t aH[4] = {pha[2 * s], phb[2 * s], pha[2 * s + 1], phb[2 * s + 1]};
            #pragma unroll
            for (int b = 0; b < 4; b++) {
                const int krow = s * 16 + (lane & 15);
                const uint32_t va = stV + krow * 128 +
                    (((b * 2 + (lane >> 4)) ^ (krow & 7)) << 4);
                uint32_t h0, h1, h2, h3, l0, l1, l2, l3;
                LDSM_X4T(h0, h1, h2, h3, va);
                MMA_F16(oacc[2 * b],     aH, h0, h1);
                MMA_F16(oacc[2 * b + 1], aH, h2, h3);
                LDSM_X4T(l0, l1, l2, l3, va + 8192);
                MMA_F16(oacc[2 * b],     aH, l0, l1);
                MMA_F16(oacc[2 * b + 1], aH, l2, l3);
            }
        }
    }

    // ---- epilogue: normalize, bf16 hi/lo split, write [B,T,H*HD]
    const float inva = 1.0f / la, invb = 1.0f / lb;
    const int bidx = bh >> 4, h = bh & 15;
    const long rowa = ((long)(bidx * T_ + qbase + tg)) * D_ + h * HD_;
    const long rowb = rowa + 8L * D_;
    #pragma unroll
    for (int j = 0; j < 8; j++) {
        const int col = 8 * j + 2 * ti;
        float f0 = oacc[j][0] * inva, f1 = oacc[j][1] * inva;
        float f2 = oacc[j][2] * invb, f3 = oacc[j][3] * invb;
        uint32_t hpa = pack2bf(f0, f1);
        uint32_t hpb = pack2bf(f2, f3);
        *(uint32_t*)(g_ahi + rowa + col) = hpa;
        *(uint32_t*)(g_alo + rowa + col) = resid2bf(hpa, f0, f1);
        *(uint32_t*)(g_ahi + rowb + col) = hpb;
        *(uint32_t*)(g_alo + rowb + col) = resid2bf(hpb, f2, f3);
    }
}

// ---------------------------------------------------------------------------
extern "C" void kernel_launch(void* const* d_in, const int* in_sizes, int n_in,
                              void* d_out, int out_size)
{
    const float* x      = (const float*)d_in[0];
    const float* w_qkv  = (const float*)d_in[1];
    const float* b_qkv  = (const float*)d_in[2];
    const float* w_proj = (const float*)d_in[3];
    const float* b_proj = (const float*)d_in[4];
    float* out = (float*)d_out;

    __nv_bfloat16 *xhi, *xlo, *wqhi, *wqlo, *wphi, *wplo, *ahi, *alo;
    cudaGetSymbolAddress((void**)&xhi,  g_xhi);
    cudaGetSymbolAddress((void**)&xlo,  g_xlo);
    cudaGetSymbolAddress((void**)&wqhi, g_wqhi);
    cudaGetSymbolAddress((void**)&wqlo, g_wqlo);
    cudaGetSymbolAddress((void**)&wphi, g_wphi);
    cudaGetSymbolAddress((void**)&wplo, g_wplo);
    cudaGetSymbolAddress((void**)&ahi,  g_ahi);
    cudaGetSymbolAddress((void**)&alo,  g_alo);

    // 0) bf16 hi/lo splits
    split_kernel<<<(M_ * D_) / 1024, 256>>>(x, xhi, xlo, M_ * D_);
    split_kernel<<<(D_ * 3 * D_) / 1024, 256>>>(w_qkv, wqhi, wqlo, D_ * 3 * D_);
    split_kernel<<<(D_ * D_) / 1024, 256>>>(w_proj, wphi, wplo, D_ * D_);

    // 1) QKV GEMM (bf16x3) -> q (scaled) / k bf16 hi/lo, v fp16 hi/lo
    cudaFuncSetAttribute((const void*)gemm_bf16x3<1>,
                         cudaFuncAttributeMaxDynamicSharedMemorySize, GEMM_SMEM);
    gemm_bf16x3<1><<<dim3(3 * D_ / 128, M_ / 128), 256, GEMM_SMEM>>>(
        xhi, xlo, wqhi, wqlo, b_qkv, nullptr, 3 * D_);

    // 2) tensor-core flash attention
    cudaFuncSetAttribute((const void*)attn_tc_kernel,
                         cudaFuncAttributeMaxDynamicSharedMemorySize, ATTN_SMEM);
    attn_tc_kernel<<<dim3(T_ / 128, B_ * H_), 256, ATTN_SMEM>>>();

    // 3) proj GEMM (bf16x3)
    cudaFuncSetAttribute((const void*)gemm_bf16x3<0>,
                         cudaFuncAttributeMaxDynamicSharedMemorySize, GEMM_SMEM);
    gemm_bf16x3<0><<<dim3(D_ / 128, M_ / 128), 256, GEMM_SMEM>>>(
        ahi, alo, wphi, wplo, b_proj, out, D_);
}

// round 9
// speedup vs baseline: 1.1970x; 1.0027x over previous
#include <cuda_runtime.h>
#include <cuda_bf16.h>
#include <cuda_fp16.h>
#include <cstdint>

// Problem constants
#define B_  4
#define T_  2048
#define D_  1024
#define H_  16
#define HD_ 64
#define M_  (B_ * T_)        // 8192

// Scratch (device globals — no allocation allowed)
__device__ __nv_bfloat16 g_qh[B_ * H_ * T_ * HD_];   // q (pre-scaled) bf16 hi/lo
__device__ __nv_bfloat16 g_ql[B_ * H_ * T_ * HD_];
__device__ __nv_bfloat16 g_kh[B_ * H_ * T_ * HD_];   // k bf16 hi/lo
__device__ __nv_bfloat16 g_kl[B_ * H_ * T_ * HD_];
__device__ __half        g_vh[B_ * H_ * T_ * HD_];   // v fp16 hi/lo
__device__ __half        g_vl[B_ * H_ * T_ * HD_];
__device__ __nv_bfloat16 g_xhi[M_ * D_];        // x split       [M,K]
__device__ __nv_bfloat16 g_xlo[M_ * D_];
__device__ __nv_bfloat16 g_wqhi[D_ * 3 * D_];   // w_qkv split   [K,N]
__device__ __nv_bfloat16 g_wqlo[D_ * 3 * D_];
__device__ __nv_bfloat16 g_wphi[D_ * D_];       // w_proj split  [K,N]
__device__ __nv_bfloat16 g_wplo[D_ * D_];
__device__ __nv_bfloat16 g_ahi[M_ * D_];        // attention out [M,K]
__device__ __nv_bfloat16 g_alo[M_ * D_];

// ---------------------------------------------------------------------------
__device__ __forceinline__ uint32_t smem_u32(const void* p) {
    uint32_t a;
    asm("{ .reg .u64 t; cvta.to.shared.u64 t, %1; cvt.u32.u64 %0, t; }"
        : "=r"(a) : "l"(p));
    return a;
}

#define CP_ASYNC16(saddr, gaddr) \
    asm volatile("cp.async.cg.shared.global [%0], [%1], 16;" \
                 :: "r"(saddr), "l"(gaddr))
#define CP_COMMIT()  asm volatile("cp.async.commit_group;")
#define CP_WAIT1()   asm volatile("cp.async.wait_group 1;")
#define CP_WAIT0()   asm volatile("cp.async.wait_group 0;")

#define LDSM_X4(r0, r1, r2, r3, addr) \
    asm volatile("ldmatrix.sync.aligned.m8n8.x4.shared.b16 {%0,%1,%2,%3}, [%4];" \
                 : "=r"(r0), "=r"(r1), "=r"(r2), "=r"(r3) : "r"(addr))
#define LDSM_X4T(r0, r1, r2, r3, addr) \
    asm volatile("ldmatrix.sync.aligned.m8n8.x4.trans.shared.b16 {%0,%1,%2,%3}, [%4];" \
                 : "=r"(r0), "=r"(r1), "=r"(r2), "=r"(r3) : "r"(addr))

#define MMA_BF16(c, a, b0, b1) \
    asm volatile("mma.sync.aligned.m16n8k16.row.col.f32.bf16.bf16.f32 " \
        "{%0,%1,%2,%3}, {%4,%5,%6,%7}, {%8,%9}, {%0,%1,%2,%3};" \
        : "+f"((c)[0]), "+f"((c)[1]), "+f"((c)[2]), "+f"((c)[3]) \
        : "r"((a)[0]), "r"((a)[1]), "r"((a)[2]), "r"((a)[3]), "r"(b0), "r"(b1))

#define MMA_F16(c, a, b0, b1) \
    asm volatile("mma.sync.aligned.m16n8k16.row.col.f32.f16.f16.f32 " \
        "{%0,%1,%2,%3}, {%4,%5,%6,%7}, {%8,%9}, {%0,%1,%2,%3};" \
        : "+f"((c)[0]), "+f"((c)[1]), "+f"((c)[2]), "+f"((c)[3]) \
        : "r"((a)[0]), "r"((a)[1]), "r"((a)[2]), "r"((a)[3]), "r"(b0), "r"(b1))

// pack two fp32 -> bf16x2 (lo in low half)
__device__ __forceinline__ uint32_t pack2bf(float lo, float hi) {
    uint32_t r;
    asm("cvt.rn.bf16x2.f32 %0, %1, %2;" : "=r"(r) : "f"(hi), "f"(lo));
    return r;
}
// residual pack: (lo,hi) - bf16(lo,hi)
__device__ __forceinline__ uint32_t resid2bf(uint32_t h, float lo, float hi) {
    float lf = __uint_as_float(h << 16);
    float hf = __uint_as_float(h & 0xffff0000u);
    return pack2bf(lo - lf, hi - hf);
}
// pack two fp32 -> fp16x2 (lo in low half)
__device__ __forceinline__ uint32_t pack2hf(float lo, float hi) {
    uint32_t r;
    asm("cvt.rn.f16x2.f32 %0, %1, %2;" : "=r"(r) : "f"(hi), "f"(lo));
    return r;
}
__device__ __forceinline__ uint32_t resid2hf(uint32_t h, float lo, float hi) {
    __half2 hh = *reinterpret_cast<__half2*>(&h);
    return pack2hf(lo - __half2float(hh.x), hi - __half2float(hh.y));
}
__device__ __forceinline__ float ex2(float x) {
    float r;
    asm("ex2.approx.f32 %0, %1;" : "=f"(r) : "f"(x));
    return r;
}

// ---------------------------------------------------------------------------
// Prep: elementwise fp32 -> bf16 hi/lo split
// ---------------------------------------------------------------------------
__global__ void split_kernel(const float* __restrict__ src,
                             __nv_bfloat16* __restrict__ hi,
                             __nv_bfloat16* __restrict__ lo, int n)
{
    int i = (blockIdx.x * 256 + threadIdx.x) * 4;
    if (i >= n) return;
    float4 v = *(const float4*)(src + i);
    uint32_t h0 = pack2bf(v.x, v.y), h1 = pack2bf(v.z, v.w);
    uint32_t l0 = resid2bf(h0, v.x, v.y), l1 = resid2bf(h1, v.z, v.w);
    *(uint2*)(hi + i) = make_uint2(h0, h1);
    *(uint2*)(lo + i) = make_uint2(l0, l1);
}

// ---------------------------------------------------------------------------
// bf16x3 GEMM via mma.sync — R6/R8 configuration (16 warps/SM).
// 8 warps, 64x32 warp tiles, 3-stage cp.async pipeline, 1 sync/chunk.
// EPI=0: plain store.  EPI=1: QKV scatter (q pre-scaled by SCL2, bf16 hi/lo;
// k bf16 hi/lo; v fp16 hi/lo).
// ---------------------------------------------------------------------------
#define GEMM_SMEM (3 * 32768)
#define SCL2 0.1803368801111204f   // 0.125 * log2(e)

template <int EPI>
__global__ __launch_bounds__(256, 2) void gemm_bf16x3(
    const __nv_bfloat16* __restrict__ Ahi, const __nv_bfloat16* __restrict__ Alo,
    const __nv_bfloat16* __restrict__ Bhi, const __nv_bfloat16* __restrict__ Blo,
    const float* __restrict__ bias, float* __restrict__ C, int N)
{
    extern __shared__ char sm[];
    const uint32_t sb = smem_u32(sm);
    const int tid = threadIdx.x;
    const int warp = tid >> 5, lane = tid & 31;
    const int m0 = blockIdx.y * 128, n0 = blockIdx.x * 128;
    const int K = 1024;

    const int a_r0 = (tid * 2) >> 2,     a_c0 = (tid * 2) & 3;
    const int a_r1 = (tid * 2 + 1) >> 2, a_c1 = (tid * 2 + 1) & 3;
    const int b_r0 = (tid * 2) >> 4,     b_c0 = (tid * 2) & 15;
    const int b_r1 = (tid * 2 + 1) >> 4, b_c1 = (tid * 2 + 1) & 15;

    auto load_stage = [&](int c, int buf) {
        const uint32_t st = sb + buf * 32768;
        #pragma unroll
        for (int part = 0; part < 2; part++) {
            const __nv_bfloat16* Ap = part ? Alo : Ahi;
            const __nv_bfloat16* Bp = part ? Blo : Bhi;
            const uint32_t ao = st + part * 8192;
            const uint32_t bo = st + 16384 + part * 8192;
            CP_ASYNC16(ao + a_r0 * 64 + ((a_c0 ^ (a_r0 & 3)) << 4),
                       Ap + (long)(m0 + a_r0) * K + c * 32 + a_c0 * 8);
            CP_ASYNC16(ao + a_r1 * 64 + ((a_c1 ^ (a_r1 & 3)) << 4),
                       Ap + (long)(m0 + a_r1) * K + c * 32 + a_c1 * 8);
            CP_ASYNC16(bo + b_r0 * 256 + ((b_c0 ^ (b_r0 & 7)) << 4),
                       Bp + (long)(c * 32 + b_r0) * N + n0 + b_c0 * 8);
            CP_ASYNC16(bo + b_r1 * 256 + ((b_c1 ^ (b_r1 & 7)) << 4),
                       Bp + (long)(c * 32 + b_r1) * N + n0 + b_c1 * 8);
        }
        CP_COMMIT();
    };

    const int wm = (warp & 1) * 64;
    const int wn = (warp >> 1) * 32;

    float acc[4][4][4] = {};

    const int a_lr = lane & 15;
    const int a_lk = lane >> 4;
    const int b_lk = lane & 15;
    const int b_ln = lane >> 4;
    const int nu0 = wn >> 3;

    load_stage(0, 0);
    load_stage(1, 1);

    int buf = 0;                 // c % 3
    for (int c = 0; c < 32; c++) {
        if (c < 31) CP_WAIT1(); else CP_WAIT0();
        __syncthreads();
        if (c + 2 < 32) {
            int nb = buf + 2; if (nb >= 3) nb -= 3;
            load_stage(c + 2, nb);
        }

        const uint32_t st = sb + buf * 32768;
        #pragma unroll
        for (int ks = 0; ks < 2; ks++) {
            uint32_t ah[4][4], al[4][4];
            #pragma unroll
            for (int mi = 0; mi < 4; mi++) {
                const int row = wm + mi * 16 + a_lr;
                const int ku = ks * 2 + a_lk;
                const uint32_t off = row * 64 + ((ku ^ (row & 3)) << 4);
                LDSM_X4(ah[mi][0], ah[mi][1], ah[mi][2], ah[mi][3], st + off);
                LDSM_X4(al[mi][0], al[mi][1], al[mi][2], al[mi][3], st + 8192 + off);
            }
            #pragma unroll
            for (int bi = 0; bi < 2; bi++) {
                const int krow = ks * 16 + b_lk;
                const int nu = nu0 + bi * 2 + b_ln;
                const uint32_t boff = krow * 256 + ((nu ^ (krow & 7)) << 4);
                uint32_t bh[4], bl[4];
                LDSM_X4T(bh[0], bh[1], bh[2], bh[3], st + 16384 + boff);
                LDSM_X4T(bl[0], bl[1], bl[2], bl[3], st + 24576 + boff);
                #pragma unroll
                for (int mi = 0; mi < 4; mi++) {
                    MMA_BF16(acc[mi][bi * 2],     ah[mi], bh[0], bh[1]);
                    MMA_BF16(acc[mi][bi * 2],     ah[mi], bl[0], bl[1]);
                    MMA_BF16(acc[mi][bi * 2],     al[mi], bh[0], bh[1]);
                    MMA_BF16(acc[mi][bi * 2 + 1], ah[mi], bh[2], bh[3]);
                    MMA_BF16(acc[mi][bi * 2 + 1], ah[mi], bl[2], bl[3]);
                    MMA_BF16(acc[mi][bi * 2 + 1], al[mi], bh[2], bh[3]);
                }
            }
        }
        if (++buf == 3) buf = 0;
    }

    // Epilogue
    const int tg = lane >> 2, ti = lane & 3;
    #pragma unroll
    for (int mi = 0; mi < 4; mi++) {
        #pragma unroll
        for (int nj = 0; nj < 4; nj++) {
            const int n = n0 + wn + nj * 8 + ti * 2;
            const float bx = __ldg(&bias[n]), by = __ldg(&bias[n + 1]);
            #pragma unroll
            for (int half = 0; half < 2; half++) {
                const int m = m0 + wm + mi * 16 + tg + half * 8;
                float ox = acc[mi][nj][half * 2 + 0] + bx;
                float oy = acc[mi][nj][half * 2 + 1] + by;
                if (EPI == 0) {
                    *(float2*)(C + (long)m * N + n) = make_float2(ox, oy);
                } else {
                    const int bidx = m >> 11, t = m & (T_ - 1);
                    const int which = n >> 10;
                    const int rem = n & 1023;
                    const int h = rem >> 6, hd = rem & 63;
                    long off = (((long)bidx * H_ + h) * T_ + t) * HD_ + hd;
                    if (which == 0) {
                        ox *= SCL2; oy *= SCL2;      // pre-scale q
                        uint32_t hp = pack2bf(ox, oy);
                        *(uint32_t*)(g_qh + off) = hp;
                        *(uint32_t*)(g_ql + off) = resid2bf(hp, ox, oy);
                    } else if (which == 1) {
                        uint32_t hp = pack2bf(ox, oy);
                        *(uint32_t*)(g_kh + off) = hp;
                        *(uint32_t*)(g_kl + off) = resid2bf(hp, ox, oy);
                    } else {
                        uint32_t hp = pack2hf(ox, oy);
                        *(uint32_t*)(g_vh + off) = hp;
                        *(uint32_t*)(g_vl + off) = resid2hf(hp, ox, oy);
                    }
                }
            }
        }
    }
}

// ---------------------------------------------------------------------------
// Tensor-core causal flash attention — now 2 CTAs/SM (16 warps, the proven
// good point on the warps-vs-tensor% curve).  To fit 128 regs, Q-lo
// fragments are re-loaded from smem per chunk (4 live regs instead of 16).
// S = QK^T bf16x3 (q pre-scaled, log2 domain); PV fp16x2 (single-fp16 P).
// smem 96KB/CTA; 2 x 96 = 192KB <= 228KB.
// ---------------------------------------------------------------------------
#define ATTN_SMEM (32768 + 2 * 32768)

__global__ __launch_bounds__(256, 2) void attn_tc_kernel()
{
    extern __shared__ char sm[];
    const uint32_t sb = smem_u32(sm);
    const int tid = threadIdx.x;
    const int w = tid >> 5, lane = tid & 31;
    const int tg = lane >> 2, ti = lane & 3;
    const int qt = 15 - blockIdx.x;           // big tiles first
    const int bh = blockIdx.y;
    const int qbase = qt * 128 + w * 16;
    const int r0 = qbase + tg;                // thread rows r0, r0+8

    const long bhoff = (long)bh * T_ * HD_;

    // ---- issue Q loads (rows of 128B, swizzled) + KV tile 0
    {
        const int row = tid >> 1;
        const int u0 = (tid & 1) * 4;
        const long gq = bhoff + (long)(qt * 128 + row) * HD_;
        #pragma unroll
        for (int i = 0; i < 4; i++) {
            const int u = u0 + i;
            const uint32_t so = row * 128 + ((u ^ (row & 7)) << 4);
            CP_ASYNC16(sb + so,         g_qh + gq + u * 8);
            CP_ASYNC16(sb + 16384 + so, g_ql + gq + u * 8);
        }
    }
    const int kvp = tid >> 6;        // 0..3 -> Kh,Kl,Vh,Vl
    const int kvr = tid & 63;        // row within tile
    const char* kvsrc =
        (kvp == 0) ? (const char*)g_kh : (kvp == 1) ? (const char*)g_kl :
        (kvp == 2) ? (const char*)g_vh : (const char*)g_vl;
    const uint32_t kvdst_off = kvp * 8192 + kvr * 128;

    auto load_kv = [&](int kb, int buf) {
        const uint32_t st = sb + 32768 + buf * 32768;
        const long gs = (bhoff + (long)(kb * 64 + kvr) * HD_) * 2;  // bytes
        #pragma unroll
        for (int u = 0; u < 8; u++)
            CP_ASYNC16(st + kvdst_off + ((u ^ (kvr & 7)) << 4),
                       kvsrc + gs + u * 16);
    };
    load_kv(0, 0);
    CP_COMMIT();
    CP_WAIT0();
    __syncthreads();

    // ---- Q-hi fragments persistent; Q-lo re-loaded per chunk (reg pressure)
    uint32_t qh[4][4];
    uint32_t qlad[4];               // smem addresses for Q-lo LDSM per s-step
    #pragma unroll
    for (int s = 0; s < 4; s++) {
        const int row = w * 16 + (lane & 15);
        const int ku = s * 2 + (lane >> 4);
        const uint32_t ad = sb + row * 128 + ((ku ^ (row & 7)) << 4);
        LDSM_X4(qh[s][0], qh[s][1], qh[s][2], qh[s][3], ad);
        qlad[s] = ad + 16384;
    }

    float oacc[8][4] = {};
    float m2a = -1e30f, m2b = -1e30f;
    float la = 0.f, lb = 0.f;

    const int nt = 2 * qt + 2;
    for (int kb = 0; kb < nt; kb++) {
        if (kb > 0) CP_WAIT0();
        __syncthreads();
        if (kb + 1 < nt) { load_kv(kb + 1, (kb + 1) & 1); CP_COMMIT(); }

        if (kb * 64 > qbase + 15) continue;   // warp fully masked

        const uint32_t stK = sb + 32768 + (kb & 1) * 32768;
        const uint32_t stV = stK + 16384;

        // ---- S = Q K^T (bf16x3, already log2-scaled via q)
        float sacc[8][4] = {};
        #pragma unroll
        for (int s = 0; s < 4; s++) {
            uint32_t qls[4];
            LDSM_X4(qls[0], qls[1], qls[2], qls[3], qlad[s]);
            #pragma unroll
            for (int g = 0; g < 4; g++) {
                const int row = g * 16 + (lane & 15);
                const uint32_t ka = stK + row * 128 +
                    (((s * 2 + (lane >> 4)) ^ (row & 7)) << 4);
                uint32_t h0, h1, h2, h3, l0, l1, l2, l3;
                LDSM_X4(h0, h1, h2, h3, ka);
                LDSM_X4(l0, l1, l2, l3, ka + 8192);
                MMA_BF16(sacc[2 * g],     qh[s], h0, h2);
                MMA_BF16(sacc[2 * g],     qls,   h0, h2);
                MMA_BF16(sacc[2 * g],     qh[s], l0, l2);
                MMA_BF16(sacc[2 * g + 1], qh[s], h1, h3);
                MMA_BF16(sacc[2 * g + 1], qls,   h1, h3);
                MMA_BF16(sacc[2 * g + 1], qh[s], l1, l3);
            }
        }

        // ---- causal mask + row max (values already in log2 domain)
        const bool needmask = (kb * 64 + 63) > r0;
        float mra = -1e30f, mrb = -1e30f;
        #pragma unroll
        for (int j = 0; j < 8; j++) {
            const int c0 = kb * 64 + 8 * j + 2 * ti, c1 = c0 + 1;
            float z0 = sacc[j][0];
            float z1 = sacc[j][1];
            float z2 = sacc[j][2];
            float z3 = sacc[j][3];
            if (needmask) {
                if (c0 > r0) z0 = -1e30f;
                if (c1 > r0) z1 = -1e30f;
                if (c0 > r0 + 8) z2 = -1e30f;
                if (c1 > r0 + 8) z3 = -1e30f;
            }
            sacc[j][0] = z0; sacc[j][1] = z1; sacc[j][2] = z2; sacc[j][3] = z3;
            mra = fmaxf(mra, fmaxf(z0, z1));
            mrb = fmaxf(mrb, fmaxf(z2, z3));
        }
        mra = fmaxf(mra, __shfl_xor_sync(0xffffffffu, mra, 1));
        mra = fmaxf(mra, __shfl_xor_sync(0xffffffffu, mra, 2));
        mrb = fmaxf(mrb, __shfl_xor_sync(0xffffffffu, mrb, 1));
        mrb = fmaxf(mrb, __shfl_xor_sync(0xffffffffu, mrb, 2));

        const float mna = fmaxf(m2a, mra);
        const float mnb = fmaxf(m2b, mrb);
        const float alpa = ex2(m2a - mna);
        const float alpb = ex2(m2b - mnb);
        m2a = mna; m2b = mnb;

        #pragma unroll
        for (int j = 0; j < 8; j++) {
            oacc[j][0] *= alpa; oacc[j][1] *= alpa;
            oacc[j][2] *= alpb; oacc[j][3] *= alpb;
        }

        // ---- exp + pack P to single fp16 (A-frag layout)
        uint32_t pha[8], phb[8];
        float sa = 0.f, sbm = 0.f;
        #pragma unroll
        for (int j = 0; j < 8; j++) {
            float p0 = ex2(sacc[j][0] - m2a);
            float p1 = ex2(sacc[j][1] - m2a);
            float p2 = ex2(sacc[j][2] - m2b);
            float p3 = ex2(sacc[j][3] - m2b);
            sa += p0 + p1; sbm += p2 + p3;
            pha[j] = pack2hf(p0, p1);
            phb[j] = pack2hf(p2, p3);
        }
        sa  += __shfl_xor_sync(0xffffffffu, sa, 1);
        sa  += __shfl_xor_sync(0xffffffffu, sa, 2);
        sbm += __shfl_xor_sync(0xffffffffu, sbm, 1);
        sbm += __shfl_xor_sync(0xffffffffu, sbm, 2);
        la = la * alpa + sa;
        lb = lb * alpb + sbm;

        // ---- O += P V (fp16x2: P_fp16 * (Vh + Vl))
        #pragma unroll
        for (int s = 0; s < 4; s++) {
            uint32_t aH[4] = {pha[2 * s], phb[2 * s], pha[2 * s + 1], phb[2 * s + 1]};
            #pragma unroll
            for (int b = 0; b < 4; b++) {
                const int krow = s * 16 + (lane & 15);
                const uint32_t va = stV + krow * 128 +
                    (((b * 2 + (lane >> 4)) ^ (krow & 7)) << 4);
                uint32_t h0, h1, h2, h3, l0, l1, l2, l3;
                LDSM_X4T(h0, h1, h2, h3, va);
                MMA_F16(oacc[2 * b],     aH, h0, h1);
                MMA_F16(oacc[2 * b + 1], aH, h2, h3);
                LDSM_X4T(l0, l1, l2, l3, va + 8192);
                MMA_F16(oacc[2 * b],     aH, l0, l1);
                MMA_F16(oacc[2 * b + 1], aH, l2, l3);
            }
        }
    }

    // ---- epilogue: normalize, bf16 hi/lo split, write [B,T,H*HD]
    const float inva = 1.0f / la, invb = 1.0f / lb;
    const int bidx = bh >> 4, h = bh & 15;
    const long rowa = ((long)(bidx * T_ + qbase + tg)) * D_ + h * HD_;
    const long rowb = rowa + 8L * D_;
    #pragma unroll
    for (int j = 0; j < 8; j++) {
        const int col = 8 * j + 2 * ti;
        float f0 = oacc[j][0] * inva, f1 = oacc[j][1] * inva;
        float f2 = oacc[j][2] * invb, f3 = oacc[j][3] * invb;
        uint32_t hpa = pack2bf(f0, f1);
        uint32_t hpb = pack2bf(f2, f3);
        *(uint32_t*)(g_ahi + rowa + col) = hpa;
        *(uint32_t*)(g_alo + rowa + col) = resid2bf(hpa, f0, f1);
        *(uint32_t*)(g_ahi + rowb + col) = hpb;
        *(uint32_t*)(g_alo + rowb + col) = resid2bf(hpb, f2, f3);
    }
}

// ---------------------------------------------------------------------------
extern "C" void kernel_launch(void* const* d_in, const int* in_sizes, int n_in,
                              void* d_out, int out_size)
{
    const float* x      = (const float*)d_in[0];
    const float* w_qkv  = (const float*)d_in[1];
    const float* b_qkv  = (const float*)d_in[2];
    const float* w_proj = (const float*)d_in[3];
    const float* b_proj = (const float*)d_in[4];
    float* out = (float*)d_out;

    __nv_bfloat16 *xhi, *xlo, *wqhi, *wqlo, *wphi, *wplo, *ahi, *alo;
    cudaGetSymbolAddress((void**)&xhi,  g_xhi);
    cudaGetSymbolAddress((void**)&xlo,  g_xlo);
    cudaGetSymbolAddress((void**)&wqhi, g_wqhi);
    cudaGetSymbolAddress((void**)&wqlo, g_wqlo);
    cudaGetSymbolAddress((void**)&wphi, g_wphi);
    cudaGetSymbolAddress((void**)&wplo, g_wplo);
    cudaGetSymbolAddress((void**)&ahi,  g_ahi);
    cudaGetSymbolAddress((void**)&alo,  g_alo);

    // 0) bf16 hi/lo splits
    split_kernel<<<(M_ * D_) / 1024, 256>>>(x, xhi, xlo, M_ * D_);
    split_kernel<<<(D_ * 3 * D_) / 1024, 256>>>(w_qkv, wqhi, wqlo, D_ * 3 * D_);
    split_kernel<<<(D_ * D_) / 1024, 256>>>(w_proj, wphi, wplo, D_ * D_);

    // 1) QKV GEMM (bf16x3) -> q (scaled) / k bf16 hi/lo, v fp16 hi/lo
    cudaFuncSetAttribute((const void*)gemm_bf16x3<1>,
                         cudaFuncAttributeMaxDynamicSharedMemorySize, GEMM_SMEM);
    gemm_bf16x3<1><<<dim3(3 * D_ / 128, M_ / 128), 256, GEMM_SMEM>>>(
        xhi, xlo, wqhi, wqlo, b_qkv, nullptr, 3 * D_);

    // 2) tensor-core flash attention (2 CTAs/SM)
    cudaFuncSetAttribute((const void*)attn_tc_kernel,
                         cudaFuncAttributeMaxDynamicSharedMemorySize, ATTN_SMEM);
    attn_tc_kernel<<<dim3(T_ / 128, B_ * H_), 256, ATTN_SMEM>>>();

    // 3) proj GEMM (bf16x3)
    cudaFuncSetAttribute((const void*)gemm_bf16x3<0>,
                         cudaFuncAttributeMaxDynamicSharedMemorySize, GEMM_SMEM);
    gemm_bf16x3<0><<<dim3(D_ / 128, M_ / 128), 256, GEMM_SMEM>>>(
        ahi, alo, wphi, wplo, b_proj, out, D_);
}

// round 10
// speedup vs baseline: 1.5440x; 1.2899x over previous
#include <cuda_runtime.h>
#include <cuda_bf16.h>
#include <cuda_fp16.h>
#include <cstdint>

// Problem constants
#define B_  4
#define T_  2048
#define D_  1024
#define H_  16
#define HD_ 64
#define M_  (B_ * T_)        // 8192

// Scratch (device globals — no allocation allowed)
__device__ __half g_qs[B_ * H_ * T_ * HD_];   // q single fp16, pre-scaled SCL2
__device__ __half g_kh[B_ * H_ * T_ * HD_];   // k fp16 hi/lo
__device__ __half g_kl[B_ * H_ * T_ * HD_];
__device__ __half g_vh[B_ * H_ * T_ * HD_];   // v fp16 hi/lo
__device__ __half g_vl[B_ * H_ * T_ * HD_];
__device__ __half g_xs[M_ * D_];              // x single fp16      [M,K]
__device__ __half g_wqh[D_ * 3 * D_];         // w_qkv fp16 hi/lo   [K,N]
__device__ __half g_wql[D_ * 3 * D_];
__device__ __half g_wph[D_ * D_];             // w_proj fp16 hi/lo  [K,N]
__device__ __half g_wpl[D_ * D_];
__device__ __half g_as[M_ * D_];              // attention out single fp16

// ---------------------------------------------------------------------------
__device__ __forceinline__ uint32_t smem_u32(const void* p) {
    uint32_t a;
    asm("{ .reg .u64 t; cvta.to.shared.u64 t, %1; cvt.u32.u64 %0, t; }"
        : "=r"(a) : "l"(p));
    return a;
}

#define CP_ASYNC16(saddr, gaddr) \
    asm volatile("cp.async.cg.shared.global [%0], [%1], 16;" \
                 :: "r"(saddr), "l"(gaddr))
#define CP_COMMIT()  asm volatile("cp.async.commit_group;")
#define CP_WAIT1()   asm volatile("cp.async.wait_group 1;")
#define CP_WAIT0()   asm volatile("cp.async.wait_group 0;")

#define LDSM_X4(r0, r1, r2, r3, addr) \
    asm volatile("ldmatrix.sync.aligned.m8n8.x4.shared.b16 {%0,%1,%2,%3}, [%4];" \
                 : "=r"(r0), "=r"(r1), "=r"(r2), "=r"(r3) : "r"(addr))
#define LDSM_X4T(r0, r1, r2, r3, addr) \
    asm volatile("ldmatrix.sync.aligned.m8n8.x4.trans.shared.b16 {%0,%1,%2,%3}, [%4];" \
                 : "=r"(r0), "=r"(r1), "=r"(r2), "=r"(r3) : "r"(addr))

#define MMA_F16(c, a, b0, b1) \
    asm volatile("mma.sync.aligned.m16n8k16.row.col.f32.f16.f16.f32 " \
        "{%0,%1,%2,%3}, {%4,%5,%6,%7}, {%8,%9}, {%0,%1,%2,%3};" \
        : "+f"((c)[0]), "+f"((c)[1]), "+f"((c)[2]), "+f"((c)[3]) \
        : "r"((a)[0]), "r"((a)[1]), "r"((a)[2]), "r"((a)[3]), "r"(b0), "r"(b1))

// pack two fp32 -> fp16x2 (lo in low half)
__device__ __forceinline__ uint32_t pack2hf(float lo, float hi) {
    uint32_t r;
    asm("cvt.rn.f16x2.f32 %0, %1, %2;" : "=r"(r) : "f"(hi), "f"(lo));
    return r;
}
__device__ __forceinline__ uint32_t resid2hf(uint32_t h, float lo, float hi) {
    __half2 hh = *reinterpret_cast<__half2*>(&h);
    return pack2hf(lo - __half2float(hh.x), hi - __half2float(hh.y));
}
__device__ __forceinline__ float ex2(float x) {
    float r;
    asm("ex2.approx.f32 %0, %1;" : "=f"(r) : "f"(x));
    return r;
}

// ---------------------------------------------------------------------------
// Prep kernels: fp32 -> fp16 hi/lo split (weights) and fp32 -> fp16 (x)
// ---------------------------------------------------------------------------
__global__ void split_hf(const float* __restrict__ src,
                         __half* __restrict__ hi, __half* __restrict__ lo, int n)
{
    int i = (blockIdx.x * 256 + threadIdx.x) * 4;
    if (i >= n) return;
    float4 v = *(const float4*)(src + i);
    uint32_t h0 = pack2hf(v.x, v.y), h1 = pack2hf(v.z, v.w);
    uint32_t l0 = resid2hf(h0, v.x, v.y), l1 = resid2hf(h1, v.z, v.w);
    *(uint2*)(hi + i) = make_uint2(h0, h1);
    *(uint2*)(lo + i) = make_uint2(l0, l1);
}

__global__ void conv_hf(const float* __restrict__ src,
                        __half* __restrict__ dst, int n)
{
    int i = (blockIdx.x * 256 + threadIdx.x) * 4;
    if (i >= n) return;
    float4 v = *(const float4*)(src + i);
    *(uint2*)(dst + i) = make_uint2(pack2hf(v.x, v.y), pack2hf(v.z, v.w));
}

// ---------------------------------------------------------------------------
// fp16x2 GEMM via mma.sync:  C = (A_f16) @ (Bh + Bl) + bias
// A single fp16 (activations: x / attn-out; rounding ~1.4e-4 RMS),
// B fp16 hi/lo (weights; lo parts land in fp16 subnormal range which NV
// half HW keeps — no FTZ — so B is near-exact, err ~1e-6).
// 8 warps, 64x32 warp tiles (16 warps/SM — proven optimum), 3-stage cp.async,
// 1 sync/chunk.  Stage = A 8KB + Bh 8KB + Bl 8KB = 24KB.
// EPI=0: plain store.  EPI=1: QKV scatter (q single pre-scaled; k,v hi/lo).
// ---------------------------------------------------------------------------
#define GEMM_SMEM (3 * 24576)
#define SCL2 0.1803368801111204f   // 0.125 * log2(e)

template <int EPI>
__global__ __launch_bounds__(256, 2) void gemm_f16x2(
    const __half* __restrict__ A,
    const __half* __restrict__ Bh16, const __half* __restrict__ Bl16,
    const float* __restrict__ bias, float* __restrict__ C, int N)
{
    extern __shared__ char sm[];
    const uint32_t sb = smem_u32(sm);
    const int tid = threadIdx.x;
    const int warp = tid >> 5, lane = tid & 31;
    const int m0 = blockIdx.y * 128, n0 = blockIdx.x * 128;
    const int K = 1024;

    const int a_r0 = (tid * 2) >> 2,     a_c0 = (tid * 2) & 3;
    const int a_r1 = (tid * 2 + 1) >> 2, a_c1 = (tid * 2 + 1) & 3;
    const int b_r0 = (tid * 2) >> 4,     b_c0 = (tid * 2) & 15;
    const int b_r1 = (tid * 2 + 1) >> 4, b_c1 = (tid * 2 + 1) & 15;

    auto load_stage = [&](int c, int buf) {
        const uint32_t st = sb + buf * 24576;
        // A single (8KB)
        CP_ASYNC16(st + a_r0 * 64 + ((a_c0 ^ (a_r0 & 3)) << 4),
                   A + (long)(m0 + a_r0) * K + c * 32 + a_c0 * 8);
        CP_ASYNC16(st + a_r1 * 64 + ((a_c1 ^ (a_r1 & 3)) << 4),
                   A + (long)(m0 + a_r1) * K + c * 32 + a_c1 * 8);
        // B hi/lo (8KB each)
        #pragma unroll
        for (int part = 0; part < 2; part++) {
            const __half* Bp = part ? Bl16 : Bh16;
            const uint32_t bo = st + 8192 + part * 8192;
            CP_ASYNC16(bo + b_r0 * 256 + ((b_c0 ^ (b_r0 & 7)) << 4),
                       Bp + (long)(c * 32 + b_r0) * N + n0 + b_c0 * 8);
            CP_ASYNC16(bo + b_r1 * 256 + ((b_c1 ^ (b_r1 & 7)) << 4),
                       Bp + (long)(c * 32 + b_r1) * N + n0 + b_c1 * 8);
        }
        CP_COMMIT();
    };

    const int wm = (warp & 1) * 64;
    const int wn = (warp >> 1) * 32;

    float acc[4][4][4] = {};

    const int a_lr = lane & 15;
    const int a_lk = lane >> 4;
    const int b_lk = lane & 15;
    const int b_ln = lane >> 4;
    const int nu0 = wn >> 3;

    load_stage(0, 0);
    load_stage(1, 1);

    int buf = 0;                 // c % 3
    for (int c = 0; c < 32; c++) {
        if (c < 31) CP_WAIT1(); else CP_WAIT0();
        __syncthreads();
        if (c + 2 < 32) {
            int nb = buf + 2; if (nb >= 3) nb -= 3;
            load_stage(c + 2, nb);
        }

        const uint32_t st = sb + buf * 24576;
        #pragma unroll
        for (int ks = 0; ks < 2; ks++) {
            uint32_t ah[4][4];
            #pragma unroll
            for (int mi = 0; mi < 4; mi++) {
                const int row = wm + mi * 16 + a_lr;
                const int ku = ks * 2 + a_lk;
                const uint32_t off = row * 64 + ((ku ^ (row & 3)) << 4);
                LDSM_X4(ah[mi][0], ah[mi][1], ah[mi][2], ah[mi][3], st + off);
            }
            #pragma unroll
            for (int bi = 0; bi < 2; bi++) {
                const int krow = ks * 16 + b_lk;
                const int nu = nu0 + bi * 2 + b_ln;
                const uint32_t boff = krow * 256 + ((nu ^ (krow & 7)) << 4);
                uint32_t bh[4], bl[4];
                LDSM_X4T(bh[0], bh[1], bh[2], bh[3], st + 8192 + boff);
                LDSM_X4T(bl[0], bl[1], bl[2], bl[3], st + 16384 + boff);
                #pragma unroll
                for (int mi = 0; mi < 4; mi++) {
                    MMA_F16(acc[mi][bi * 2],     ah[mi], bh[0], bh[1]);
                    MMA_F16(acc[mi][bi * 2],     ah[mi], bl[0], bl[1]);
                    MMA_F16(acc[mi][bi * 2 + 1], ah[mi], bh[2], bh[3]);
                    MMA_F16(acc[mi][bi * 2 + 1], ah[mi], bl[2], bl[3]);
                }
            }
        }
        if (++buf == 3) buf = 0;
    }

    // Epilogue
    const int tg = lane >> 2, ti = lane & 3;
    #pragma unroll
    for (int mi = 0; mi < 4; mi++) {
        #pragma unroll
        for (int nj = 0; nj < 4; nj++) {
            const int n = n0 + wn + nj * 8 + ti * 2;
            const float bx = __ldg(&bias[n]), by = __ldg(&bias[n + 1]);
            #pragma unroll
            for (int half = 0; half < 2; half++) {
                const int m = m0 + wm + mi * 16 + tg + half * 8;
                float ox = acc[mi][nj][half * 2 + 0] + bx;
                float oy = acc[mi][nj][half * 2 + 1] + by;
                if (EPI == 0) {
                    *(float2*)(C + (long)m * N + n) = make_float2(ox, oy);
                } else {
                    const int bidx = m >> 11, t = m & (T_ - 1);
                    const int which = n >> 10;
                    const int rem = n & 1023;
                    const int h = rem >> 6, hd = rem & 63;
                    long off = (((long)bidx * H_ + h) * T_ + t) * HD_ + hd;
                    if (which == 0) {
                        *(uint32_t*)(g_qs + off) = pack2hf(ox * SCL2, oy * SCL2);
                    } else if (which == 1) {
                        uint32_t hp = pack2hf(ox, oy);
                        *(uint32_t*)(g_kh + off) = hp;
                        *(uint32_t*)(g_kl + off) = resid2hf(hp, ox, oy);
                    } else {
                        uint32_t hp = pack2hf(ox, oy);
                        *(uint32_t*)(g_vh + off) = hp;
                        *(uint32_t*)(g_vl + off) = resid2hf(hp, ox, oy);
                    }
                }
            }
        }
    }
}

// ---------------------------------------------------------------------------
// Tensor-core causal flash attention, all-fp16 operands:
// S = q_f16 * (Kh + Kl)  (q pre-scaled to log2 domain; 64 mma/chunk, was 96)
// PV = P_f16 * (Vh + Vl) (64 mma/chunk)
// q single => no ql fragments => real 2 CTAs/SM at 128 regs.
// smem: Q 16KB + 2 stages x (Kh,Kl,Vh,Vl 8KB) = 80KB/CTA; 2x80=160 <= 228KB.
// ---------------------------------------------------------------------------
#define ATTN_SMEM (16384 + 2 * 32768)

__global__ __launch_bounds__(256, 2) void attn_tc_kernel()
{
    extern __shared__ char sm[];
    const uint32_t sb = smem_u32(sm);
    const int tid = threadIdx.x;
    const int w = tid >> 5, lane = tid & 31;
    const int tg = lane >> 2, ti = lane & 3;
    const int qt = 15 - blockIdx.x;           // big tiles first
    const int bh = blockIdx.y;
    const int qbase = qt * 128 + w * 16;
    const int r0 = qbase + tg;                // thread rows r0, r0+8

    const long bhoff = (long)bh * T_ * HD_;

    // ---- issue Q loads (rows of 128B, swizzled) + KV tile 0
    {
        const int row = tid >> 1;
        const int u0 = (tid & 1) * 4;
        const long gq = bhoff + (long)(qt * 128 + row) * HD_;
        #pragma unroll
        for (int i = 0; i < 4; i++) {
            const int u = u0 + i;
            CP_ASYNC16(sb + row * 128 + ((u ^ (row & 7)) << 4), g_qs + gq + u * 8);
        }
    }
    const int kvp = tid >> 6;        // 0..3 -> Kh,Kl,Vh,Vl
    const int kvr = tid & 63;        // row within tile
    const __half* kvsrc =
        (kvp == 0) ? g_kh : (kvp == 1) ? g_kl : (kvp == 2) ? g_vh : g_vl;
    const uint32_t kvdst_off = kvp * 8192 + kvr * 128;

    auto load_kv = [&](int kb, int buf) {
        const uint32_t st = sb + 16384 + buf * 32768;
        const long gs = bhoff + (long)(kb * 64 + kvr) * HD_;
        #pragma unroll
        for (int u = 0; u < 8; u++)
            CP_ASYNC16(st + kvdst_off + ((u ^ (kvr & 7)) << 4), kvsrc + gs + u * 8);
    };
    load_kv(0, 0);
    CP_COMMIT();
    CP_WAIT0();
    __syncthreads();

    // ---- Q fragments (single fp16, pre-scaled)
    uint32_t qh[4][4];
    #pragma unroll
    for (int s = 0; s < 4; s++) {
        const int row = w * 16 + (lane & 15);
        const int ku = s * 2 + (lane >> 4);
        const uint32_t ad = sb + row * 128 + ((ku ^ (row & 7)) << 4);
        LDSM_X4(qh[s][0], qh[s][1], qh[s][2], qh[s][3], ad);
    }

    float oacc[8][4] = {};
    float m2a = -1e30f, m2b = -1e30f;
    float la = 0.f, lb = 0.f;

    const int nt = 2 * qt + 2;
    for (int kb = 0; kb < nt; kb++) {
        if (kb > 0) CP_WAIT0();
        __syncthreads();
        if (kb + 1 < nt) { load_kv(kb + 1, (kb + 1) & 1); CP_COMMIT(); }

        if (kb * 64 > qbase + 15) continue;   // warp fully masked

        const uint32_t stK = sb + 16384 + (kb & 1) * 32768;
        const uint32_t stV = stK + 16384;

        // ---- S = q (Kh + Kl)   (log2 domain already)
        float sacc[8][4] = {};
        #pragma unroll
        for (int s = 0; s < 4; s++) {
            #pragma unroll
            for (int g = 0; g < 4; g++) {
                const int row = g * 16 + (lane & 15);
                const uint32_t ka = stK + row * 128 +
                    (((s * 2 + (lane >> 4)) ^ (row & 7)) << 4);
                uint32_t h0, h1, h2, h3, l0, l1, l2, l3;
                LDSM_X4(h0, h1, h2, h3, ka);
                LDSM_X4(l0, l1, l2, l3, ka + 8192);
                MMA_F16(sacc[2 * g],     qh[s], h0, h2);
                MMA_F16(sacc[2 * g],     qh[s], l0, l2);
                MMA_F16(sacc[2 * g + 1], qh[s], h1, h3);
                MMA_F16(sacc[2 * g + 1], qh[s], l1, l3);
            }
        }

        // ---- causal mask + row max (values already in log2 domain)
        const bool needmask = (kb * 64 + 63) > r0;
        float mra = -1e30f, mrb = -1e30f;
        #pragma unroll
        for (int j = 0; j < 8; j++) {
            const int c0 = kb * 64 + 8 * j + 2 * ti, c1 = c0 + 1;
            float z0 = sacc[j][0];
            float z1 = sacc[j][1];
            float z2 = sacc[j][2];
            float z3 = sacc[j][3];
            if (needmask) {
                if (c0 > r0) z0 = -1e30f;
                if (c1 > r0) z1 = -1e30f;
                if (c0 > r0 + 8) z2 = -1e30f;
                if (c1 > r0 + 8) z3 = -1e30f;
            }
            sacc[j][0] = z0; sacc[j][1] = z1; sacc[j][2] = z2; sacc[j][3] = z3;
            mra = fmaxf(mra, fmaxf(z0, z1));
            mrb = fmaxf(mrb, fmaxf(z2, z3));
        }
        mra = fmaxf(mra, __shfl_xor_sync(0xffffffffu, mra, 1));
        mra = fmaxf(mra, __shfl_xor_sync(0xffffffffu, mra, 2));
        mrb = fmaxf(mrb, __shfl_xor_sync(0xffffffffu, mrb, 1));
        mrb = fmaxf(mrb, __shfl_xor_sync(0xffffffffu, mrb, 2));

        const float mna = fmaxf(m2a, mra);
        const float mnb = fmaxf(m2b, mrb);
        const float alpa = ex2(m2a - mna);
        const float alpb = ex2(m2b - mnb);
        m2a = mna; m2b = mnb;

        #pragma unroll
        for (int j = 0; j < 8; j++) {
            oacc[j][0] *= alpa; oacc[j][1] *= alpa;
            oacc[j][2] *= alpb; oacc[j][3] *= alpb;
        }

        // ---- exp + pack P to single fp16 (A-frag layout)
        uint32_t pha[8], phb[8];
        float sa = 0.f, sbm = 0.f;
        #pragma unroll
        for (int j = 0; j < 8; j++) {
            float p0 = ex2(sacc[j][0] - m2a);
            float p1 = ex2(sacc[j][1] - m2a);
            float p2 = ex2(sacc[j][2] - m2b);
            float p3 = ex2(sacc[j][3] - m2b);
            sa += p0 + p1; sbm += p2 + p3;
            pha[j] = pack2hf(p0, p1);
            phb[j] = pack2hf(p2, p3);
        }
        sa  += __shfl_xor_sync(0xffffffffu, sa, 1);
        sa  += __shfl_xor_sync(0xffffffffu, sa, 2);
        sbm += __shfl_xor_sync(0xffffffffu, sbm, 1);
        sbm += __shfl_xor_sync(0xffffffffu, sbm, 2);
        la = la * alpa + sa;
        lb = lb * alpb + sbm;

        // ---- O += P (Vh + Vl)
        #pragma unroll
        for (int s = 0; s < 4; s++) {
            uint32_t aH[4] = {pha[2 * s], phb[2 * s], pha[2 * s + 1], phb[2 * s + 1]};
            #pragma unroll
            for (int b = 0; b < 4; b++) {
                const int krow = s * 16 + (lane & 15);
                const uint32_t va = stV + krow * 128 +
                    (((b * 2 + (lane >> 4)) ^ (krow & 7)) << 4);
                uint32_t h0, h1, h2, h3, l0, l1, l2, l3;
                LDSM_X4T(h0, h1, h2, h3, va);
                MMA_F16(oacc[2 * b],     aH, h0, h1);
                MMA_F16(oacc[2 * b + 1], aH, h2, h3);
                LDSM_X4T(l0, l1, l2, l3, va + 8192);
                MMA_F16(oacc[2 * b],     aH, l0, l1);
                MMA_F16(oacc[2 * b + 1], aH, l2, l3);
            }
        }
    }

    // ---- epilogue: normalize, single fp16, write [B,T,H*HD]
    const float inva = 1.0f / la, invb = 1.0f / lb;
    const int bidx = bh >> 4, h = bh & 15;
    const long rowa = ((long)(bidx * T_ + qbase + tg)) * D_ + h * HD_;
    const long rowb = rowa + 8L * D_;
    #pragma unroll
    for (int j = 0; j < 8; j++) {
        const int col = 8 * j + 2 * ti;
        *(uint32_t*)(g_as + rowa + col) = pack2hf(oacc[j][0] * inva, oacc[j][1] * inva);
        *(uint32_t*)(g_as + rowb + col) = pack2hf(oacc[j][2] * invb, oacc[j][3] * invb);
    }
}

// ---------------------------------------------------------------------------
extern "C" void kernel_launch(void* const* d_in, const int* in_sizes, int n_in,
                              void* d_out, int out_size)
{
    const float* x      = (const float*)d_in[0];
    const float* w_qkv  = (const float*)d_in[1];
    const float* b_qkv  = (const float*)d_in[2];
    const float* w_proj = (const float*)d_in[3];
    const float* b_proj = (const float*)d_in[4];
    float* out = (float*)d_out;

    __half *xs, *wqh, *wql, *wph, *wpl, *as;
    cudaGetSymbolAddress((void**)&xs,  g_xs);
    cudaGetSymbolAddress((void**)&wqh, g_wqh);
    cudaGetSymbolAddress((void**)&wql, g_wql);
    cudaGetSymbolAddress((void**)&wph, g_wph);
    cudaGetSymbolAddress((void**)&wpl, g_wpl);
    cudaGetSymbolAddress((void**)&as,  g_as);

    // 0) conversions: x -> fp16 single; weights -> fp16 hi/lo
    conv_hf<<<(M_ * D_) / 1024, 256>>>(x, xs, M_ * D_);
    split_hf<<<(D_ * 3 * D_) / 1024, 256>>>(w_qkv, wqh, wql, D_ * 3 * D_);
    split_hf<<<(D_ * D_) / 1024, 256>>>(w_proj, wph, wpl, D_ * D_);

    // 1) QKV GEMM (fp16x2) -> q single (scaled), k/v fp16 hi/lo
    cudaFuncSetAttribute((const void*)gemm_f16x2<1>,
                         cudaFuncAttributeMaxDynamicSharedMemorySize, GEMM_SMEM);
    gemm_f16x2<1><<<dim3(3 * D_ / 128, M_ / 128), 256, GEMM_SMEM>>>(
        xs, wqh, wql, b_qkv, nullptr, 3 * D_);

    // 2) tensor-core flash attention (fp16, 2 CTAs/SM)
    cudaFuncSetAttribute((const void*)attn_tc_kernel,
                         cudaFuncAttributeMaxDynamicSharedMemorySize, ATTN_SMEM);
    attn_tc_kernel<<<dim3(T_ / 128, B_ * H_), 256, ATTN_SMEM>>>();

    // 3) proj GEMM (fp16x2)
    cudaFuncSetAttribute((const void*)gemm_f16x2<0>,
                         cudaFuncAttributeMaxDynamicSharedMemorySize, GEMM_SMEM);
    gemm_f16x2<0><<<dim3(D_ / 128, M_ / 128), 256, GEMM_SMEM>>>(
        as, wph, wpl, b_proj, out, D_);
}

// round 11
// speedup vs baseline: 2.0303x; 1.3149x over previous
#include <cuda_runtime.h>
#include <cuda_fp16.h>
#include <cstdint>

// Problem constants
#define B_  4
#define T_  2048
#define D_  1024
#define H_  16
#define HD_ 64
#define M_  (B_ * T_)        // 8192

// Scratch (device globals — no allocation allowed)
__device__ __half g_qs[B_ * H_ * T_ * HD_];   // q single fp16, pre-scaled SCL2
__device__ __half g_ks[B_ * H_ * T_ * HD_];   // k single fp16
__device__ __half g_vh[B_ * H_ * T_ * HD_];   // v fp16 hi/lo
__device__ __half g_vl[B_ * H_ * T_ * HD_];
__device__ __half g_xs[M_ * D_];              // x single fp16      [M,K]
__device__ __half g_wq[D_ * 3 * D_];          // w_qkv single fp16  [K,N]
__device__ __half g_wph[D_ * D_];             // w_proj fp16 hi/lo  [K,N]
__device__ __half g_wpl[D_ * D_];
__device__ __half g_as[M_ * D_];              // attention out single fp16

// ---------------------------------------------------------------------------
__device__ __forceinline__ uint32_t smem_u32(const void* p) {
    uint32_t a;
    asm("{ .reg .u64 t; cvta.to.shared.u64 t, %1; cvt.u32.u64 %0, t; }"
        : "=r"(a) : "l"(p));
    return a;
}

#define CP_ASYNC16(saddr, gaddr) \
    asm volatile("cp.async.cg.shared.global [%0], [%1], 16;" \
                 :: "r"(saddr), "l"(gaddr))
#define CP_COMMIT()  asm volatile("cp.async.commit_group;")
#define CP_WAIT1()   asm volatile("cp.async.wait_group 1;")
#define CP_WAIT0()   asm volatile("cp.async.wait_group 0;")

#define LDSM_X4(r0, r1, r2, r3, addr) \
    asm volatile("ldmatrix.sync.aligned.m8n8.x4.shared.b16 {%0,%1,%2,%3}, [%4];" \
                 : "=r"(r0), "=r"(r1), "=r"(r2), "=r"(r3) : "r"(addr))
#define LDSM_X4T(r0, r1, r2, r3, addr) \
    asm volatile("ldmatrix.sync.aligned.m8n8.x4.trans.shared.b16 {%0,%1,%2,%3}, [%4];" \
                 : "=r"(r0), "=r"(r1), "=r"(r2), "=r"(r3) : "r"(addr))

#define MMA_F16(c, a, b0, b1) \
    asm volatile("mma.sync.aligned.m16n8k16.row.col.f32.f16.f16.f32 " \
        "{%0,%1,%2,%3}, {%4,%5,%6,%7}, {%8,%9}, {%0,%1,%2,%3};" \
        : "+f"((c)[0]), "+f"((c)[1]), "+f"((c)[2]), "+f"((c)[3]) \
        : "r"((a)[0]), "r"((a)[1]), "r"((a)[2]), "r"((a)[3]), "r"(b0), "r"(b1))

// pack two fp32 -> fp16x2 (lo in low half)
__device__ __forceinline__ uint32_t pack2hf(float lo, float hi) {
    uint32_t r;
    asm("cvt.rn.f16x2.f32 %0, %1, %2;" : "=r"(r) : "f"(hi), "f"(lo));
    return r;
}
__device__ __forceinline__ uint32_t resid2hf(uint32_t h, float lo, float hi) {
    __half2 hh = *reinterpret_cast<__half2*>(&h);
    return pack2hf(lo - __half2float(hh.x), hi - __half2float(hh.y));
}
__device__ __forceinline__ float ex2(float x) {
    float r;
    asm("ex2.approx.f32 %0, %1;" : "=f"(r) : "f"(x));
    return r;
}

// ---------------------------------------------------------------------------
// Prep kernels
// ---------------------------------------------------------------------------
__global__ void split_hf(const float* __restrict__ src,
                         __half* __restrict__ hi, __half* __restrict__ lo, int n)
{
    int i = (blockIdx.x * 256 + threadIdx.x) * 4;
    if (i >= n) return;
    float4 v = *(const float4*)(src + i);
    uint32_t h0 = pack2hf(v.x, v.y), h1 = pack2hf(v.z, v.w);
    uint32_t l0 = resid2hf(h0, v.x, v.y), l1 = resid2hf(h1, v.z, v.w);
    *(uint2*)(hi + i) = make_uint2(h0, h1);
    *(uint2*)(lo + i) = make_uint2(l0, l1);
}

__global__ void conv_hf(const float* __restrict__ src,
                        __half* __restrict__ dst, int n)
{
    int i = (blockIdx.x * 256 + threadIdx.x) * 4;
    if (i >= n) return;
    float4 v = *(const float4*)(src + i);
    *(uint2*)(dst + i) = make_uint2(pack2hf(v.x, v.y), pack2hf(v.z, v.w));
}

// ---------------------------------------------------------------------------
// fp16 GEMM via mma.sync.  BL=1: C = A @ (Bh + Bl); BL=0: C = A @ Bh.
// A single fp16.  8 warps, 64x32 warp tiles (16 warps/SM — proven optimum),
// 3-stage cp.async, 1 sync/chunk.
// EPI=0: plain fp32 store + bias.  EPI=1: QKV scatter (q single pre-scaled,
// k single, v hi/lo).
// Error note (calibrated R10 model): q/k are consumed at single-fp16
// precision anyway, so the B-lo term only shaves one of several 2.8e-4-class
// quadrature terms — dropped for the QKV GEMM (BL=0), kept for proj (BL=1).
// ---------------------------------------------------------------------------
#define SCL2 0.1803368801111204f   // 0.125 * log2(e)

template <int EPI, int BL>
__global__ __launch_bounds__(256, 2) void gemm_f16(
    const __half* __restrict__ A,
    const __half* __restrict__ Bh16, const __half* __restrict__ Bl16,
    const float* __restrict__ bias, float* __restrict__ C, int N)
{
    constexpr uint32_t STAGE = BL ? 24576 : 16384;
    extern __shared__ char sm[];
    const uint32_t sb = smem_u32(sm);
    const int tid = threadIdx.x;
    const int warp = tid >> 5, lane = tid & 31;
    const int m0 = blockIdx.y * 128, n0 = blockIdx.x * 128;
    const int K = 1024;

    const int a_r0 = (tid * 2) >> 2,     a_c0 = (tid * 2) & 3;
    const int a_r1 = (tid * 2 + 1) >> 2, a_c1 = (tid * 2 + 1) & 3;
    const int b_r0 = (tid * 2) >> 4,     b_c0 = (tid * 2) & 15;
    const int b_r1 = (tid * 2 + 1) >> 4, b_c1 = (tid * 2 + 1) & 15;

    auto load_stage = [&](int c, int buf) {
        const uint32_t st = sb + buf * STAGE;
        CP_ASYNC16(st + a_r0 * 64 + ((a_c0 ^ (a_r0 & 3)) << 4),
                   A + (long)(m0 + a_r0) * K + c * 32 + a_c0 * 8);
        CP_ASYNC16(st + a_r1 * 64 + ((a_c1 ^ (a_r1 & 3)) << 4),
                   A + (long)(m0 + a_r1) * K + c * 32 + a_c1 * 8);
        CP_ASYNC16(st + 8192 + b_r0 * 256 + ((b_c0 ^ (b_r0 & 7)) << 4),
                   Bh16 + (long)(c * 32 + b_r0) * N + n0 + b_c0 * 8);
        CP_ASYNC16(st + 8192 + b_r1 * 256 + ((b_c1 ^ (b_r1 & 7)) << 4),
                   Bh16 + (long)(c * 32 + b_r1) * N + n0 + b_c1 * 8);
        if (BL) {
            CP_ASYNC16(st + 16384 + b_r0 * 256 + ((b_c0 ^ (b_r0 & 7)) << 4),
                       Bl16 + (long)(c * 32 + b_r0) * N + n0 + b_c0 * 8);
            CP_ASYNC16(st + 16384 + b_r1 * 256 + ((b_c1 ^ (b_r1 & 7)) << 4),
                       Bl16 + (long)(c * 32 + b_r1) * N + n0 + b_c1 * 8);
        }
        CP_COMMIT();
    };

    const int wm = (warp & 1) * 64;
    const int wn = (warp >> 1) * 32;

    float acc[4][4][4] = {};

    const int a_lr = lane & 15;
    const int a_lk = lane >> 4;
    const int b_lk = lane & 15;
    const int b_ln = lane >> 4;
    const int nu0 = wn >> 3;

    load_stage(0, 0);
    load_stage(1, 1);

    int buf = 0;                 // c % 3
    for (int c = 0; c < 32; c++) {
        if (c < 31) CP_WAIT1(); else CP_WAIT0();
        __syncthreads();
        if (c + 2 < 32) {
            int nb = buf + 2; if (nb >= 3) nb -= 3;
            load_stage(c + 2, nb);
        }

        const uint32_t st = sb + buf * STAGE;
        #pragma unroll
        for (int ks = 0; ks < 2; ks++) {
            uint32_t ah[4][4];
            #pragma unroll
            for (int mi = 0; mi < 4; mi++) {
                const int row = wm + mi * 16 + a_lr;
                const int ku = ks * 2 + a_lk;
                const uint32_t off = row * 64 + ((ku ^ (row & 3)) << 4);
                LDSM_X4(ah[mi][0], ah[mi][1], ah[mi][2], ah[mi][3], st + off);
            }
            #pragma unroll
            for (int bi = 0; bi < 2; bi++) {
                const int krow = ks * 16 + b_lk;
                const int nu = nu0 + bi * 2 + b_ln;
                const uint32_t boff = krow * 256 + ((nu ^ (krow & 7)) << 4);
                uint32_t bh[4];
                LDSM_X4T(bh[0], bh[1], bh[2], bh[3], st + 8192 + boff);
                #pragma unroll
                for (int mi = 0; mi < 4; mi++) {
                    MMA_F16(acc[mi][bi * 2],     ah[mi], bh[0], bh[1]);
                    MMA_F16(acc[mi][bi * 2 + 1], ah[mi], bh[2], bh[3]);
                }
                if (BL) {
                    uint32_t bl[4];
                    LDSM_X4T(bl[0], bl[1], bl[2], bl[3], st + 16384 + boff);
                    #pragma unroll
                    for (int mi = 0; mi < 4; mi++) {
                        MMA_F16(acc[mi][bi * 2],     ah[mi], bl[0], bl[1]);
                        MMA_F16(acc[mi][bi * 2 + 1], ah[mi], bl[2], bl[3]);
                    }
                }
            }
        }
        if (++buf == 3) buf = 0;
    }

    // Epilogue
    const int tg = lane >> 2, ti = lane & 3;
    #pragma unroll
    for (int mi = 0; mi < 4; mi++) {
        #pragma unroll
        for (int nj = 0; nj < 4; nj++) {
            const int n = n0 + wn + nj * 8 + ti * 2;
            const float bx = __ldg(&bias[n]), by = __ldg(&bias[n + 1]);
            #pragma unroll
            for (int half = 0; half < 2; half++) {
                const int m = m0 + wm + mi * 16 + tg + half * 8;
                float ox = acc[mi][nj][half * 2 + 0] + bx;
                float oy = acc[mi][nj][half * 2 + 1] + by;
                if (EPI == 0) {
                    *(float2*)(C + (long)m * N + n) = make_float2(ox, oy);
                } else {
                    const int bidx = m >> 11, t = m & (T_ - 1);
                    const int which = n >> 10;
                    const int rem = n & 1023;
                    const int h = rem >> 6, hd = rem & 63;
                    long off = (((long)bidx * H_ + h) * T_ + t) * HD_ + hd;
                    if (which == 0) {
                        *(uint32_t*)(g_qs + off) = pack2hf(ox * SCL2, oy * SCL2);
                    } else if (which == 1) {
                        *(uint32_t*)(g_ks + off) = pack2hf(ox, oy);
                    } else {
                        uint32_t hp = pack2hf(ox, oy);
                        *(uint32_t*)(g_vh + off) = hp;
                        *(uint32_t*)(g_vl + off) = resid2hf(hp, ox, oy);
                    }
                }
            }
        }
    }
}

// ---------------------------------------------------------------------------
// Tensor-core causal flash attention:
// S  = q_f16 * K_f16       (both single; 32 mma/chunk)
// PV = P_f16 * (Vh + Vl)   (64 mma/chunk)
// smem: Q 16KB + 2 stages x (K 8KB + Vh 8KB + Vl 8KB) = 64KB/CTA; 2 CTAs/SM.
// ---------------------------------------------------------------------------
#define ATTN_SMEM (16384 + 2 * 24576)

__global__ __launch_bounds__(256, 2) void attn_tc_kernel()
{
    extern __shared__ char sm[];
    const uint32_t sb = smem_u32(sm);
    const int tid = threadIdx.x;
    const int w = tid >> 5, lane = tid & 31;
    const int tg = lane >> 2, ti = lane & 3;
    const int qt = 15 - blockIdx.x;           // big tiles first
    const int bh = blockIdx.y;
    const int qbase = qt * 128 + w * 16;
    const int r0 = qbase + tg;                // thread rows r0, r0+8

    const long bhoff = (long)bh * T_ * HD_;

    // ---- issue Q loads (rows of 128B, swizzled) + KV tile 0
    {
        const int row = tid >> 1;
        const int u0 = (tid & 1) * 4;
        const long gq = bhoff + (long)(qt * 128 + row) * HD_;
        #pragma unroll
        for (int i = 0; i < 4; i++) {
            const int u = u0 + i;
            CP_ASYNC16(sb + row * 128 + ((u ^ (row & 7)) << 4), g_qs + gq + u * 8);
        }
    }
    const int kvp = tid >> 6;        // 0..3 -> K, Vh, Vl, (idle)
    const int kvr = tid & 63;        // row within tile
    const __half* kvsrc = (kvp == 0) ? g_ks : (kvp == 1) ? g_vh : g_vl;
    const uint32_t kvdst_off = kvp * 8192 + kvr * 128;

    auto load_kv = [&](int kb, int buf) {
        if (kvp < 3) {
            const uint32_t st = sb + 16384 + buf * 24576;
            const long gs = bhoff + (long)(kb * 64 + kvr) * HD_;
            #pragma unroll
            for (int u = 0; u < 8; u++)
                CP_ASYNC16(st + kvdst_off + ((u ^ (kvr & 7)) << 4),
                           kvsrc + gs + u * 8);
        }
    };
    load_kv(0, 0);
    CP_COMMIT();
    CP_WAIT0();
    __syncthreads();

    // ---- Q fragments (single fp16, pre-scaled)
    uint32_t qh[4][4];
    #pragma unroll
    for (int s = 0; s < 4; s++) {
        const int row = w * 16 + (lane & 15);
        const int ku = s * 2 + (lane >> 4);
        const uint32_t ad = sb + row * 128 + ((ku ^ (row & 7)) << 4);
        LDSM_X4(qh[s][0], qh[s][1], qh[s][2], qh[s][3], ad);
    }

    float oacc[8][4] = {};
    float m2a = -1e30f, m2b = -1e30f;
    float la = 0.f, lb = 0.f;

    const int nt = 2 * qt + 2;
    for (int kb = 0; kb < nt; kb++) {
        if (kb > 0) CP_WAIT0();
        __syncthreads();
        if (kb + 1 < nt) { load_kv(kb + 1, (kb + 1) & 1); CP_COMMIT(); }

        if (kb * 64 > qbase + 15) continue;   // warp fully masked

        const uint32_t stK = sb + 16384 + (kb & 1) * 24576;
        const uint32_t stV = stK + 8192;

        // ---- S = q K   (log2 domain already; both single fp16)
        float sacc[8][4] = {};
        #pragma unroll
        for (int s = 0; s < 4; s++) {
            #pragma unroll
            for (int g = 0; g < 4; g++) {
                const int row = g * 16 + (lane & 15);
                const uint32_t ka = stK + row * 128 +
                    (((s * 2 + (lane >> 4)) ^ (row & 7)) << 4);
                uint32_t h0, h1, h2, h3;
                LDSM_X4(h0, h1, h2, h3, ka);
                MMA_F16(sacc[2 * g],     qh[s], h0, h2);
                MMA_F16(sacc[2 * g + 1], qh[s], h1, h3);
            }
        }

        // ---- causal mask + row max (values already in log2 domain)
        const bool needmask = (kb * 64 + 63) > r0;
        float mra = -1e30f, mrb = -1e30f;
        #pragma unroll
        for (int j = 0; j < 8; j++) {
            const int c0 = kb * 64 + 8 * j + 2 * ti, c1 = c0 + 1;
            float z0 = sacc[j][0];
            float z1 = sacc[j][1];
            float z2 = sacc[j][2];
            float z3 = sacc[j][3];
            if (needmask) {
                if (c0 > r0) z0 = -1e30f;
                if (c1 > r0) z1 = -1e30f;
                if (c0 > r0 + 8) z2 = -1e30f;
                if (c1 > r0 + 8) z3 = -1e30f;
            }
            sacc[j][0] = z0; sacc[j][1] = z1; sacc[j][2] = z2; sacc[j][3] = z3;
            mra = fmaxf(mra, fmaxf(z0, z1));
            mrb = fmaxf(mrb, fmaxf(z2, z3));
        }
        mra = fmaxf(mra, __shfl_xor_sync(0xffffffffu, mra, 1));
        mra = fmaxf(mra, __shfl_xor_sync(0xffffffffu, mra, 2));
        mrb = fmaxf(mrb, __shfl_xor_sync(0xffffffffu, mrb, 1));
        mrb = fmaxf(mrb, __shfl_xor_sync(0xffffffffu, mrb, 2));

        const float mna = fmaxf(m2a, mra);
        const float mnb = fmaxf(m2b, mrb);
        const float alpa = ex2(m2a - mna);
        const float alpb = ex2(m2b - mnb);
        m2a = mna; m2b = mnb;

        #pragma unroll
        for (int j = 0; j < 8; j++) {
            oacc[j][0] *= alpa; oacc[j][1] *= alpa;
            oacc[j][2] *= alpb; oacc[j][3] *= alpb;
        }

        // ---- exp + pack P to single fp16 (A-frag layout)
        uint32_t pha[8], phb[8];
        float sa = 0.f, sbm = 0.f;
        #pragma unroll
        for (int j = 0; j < 8; j++) {
            float p0 = ex2(sacc[j][0] - m2a);
            float p1 = ex2(sacc[j][1] - m2a);
            float p2 = ex2(sacc[j][2] - m2b);
            float p3 = ex2(sacc[j][3] - m2b);
            sa += p0 + p1; sbm += p2 + p3;
            pha[j] = pack2hf(p0, p1);
            phb[j] = pack2hf(p2, p3);
        }
        sa  += __shfl_xor_sync(0xffffffffu, sa, 1);
        sa  += __shfl_xor_sync(0xffffffffu, sa, 2);
        sbm += __shfl_xor_sync(0xffffffffu, sbm, 1);
        sbm += __shfl_xor_sync(0xffffffffu, sbm, 2);
        la = la * alpa + sa;
        lb = lb * alpb + sbm;

        // ---- O += P (Vh + Vl)
        #pragma unroll
        for (int s = 0; s < 4; s++) {
            uint32_t aH[4] = {pha[2 * s], phb[2 * s], pha[2 * s + 1], phb[2 * s + 1]};
            #pragma unroll
            for (int b = 0; b < 4; b++) {
                const int krow = s * 16 + (lane & 15);
                const uint32_t va = stV + krow * 128 +
                    (((b * 2 + (lane >> 4)) ^ (krow & 7)) << 4);
                uint32_t h0, h1, h2, h3, l0, l1, l2, l3;
                LDSM_X4T(h0, h1, h2, h3, va);
                MMA_F16(oacc[2 * b],     aH, h0, h1);
                MMA_F16(oacc[2 * b + 1], aH, h2, h3);
                LDSM_X4T(l0, l1, l2, l3, va + 8192);
                MMA_F16(oacc[2 * b],     aH, l0, l1);
                MMA_F16(oacc[2 * b + 1], aH, l2, l3);
            }
        }
    }

    // ---- epilogue: normalize, single fp16, write [B,T,H*HD]
    const float inva = 1.0f / la, invb = 1.0f / lb;
    const int bidx = bh >> 4, h = bh & 15;
    const long rowa = ((long)(bidx * T_ + qbase + tg)) * D_ + h * HD_;
    const long rowb = rowa + 8L * D_;
    #pragma unroll
    for (int j = 0; j < 8; j++) {
        const int col = 8 * j + 2 * ti;
        *(uint32_t*)(g_as + rowa + col) = pack2hf(oacc[j][0] * inva, oacc[j][1] * inva);
        *(uint32_t*)(g_as + rowb + col) = pack2hf(oacc[j][2] * invb, oacc[j][3] * invb);
    }
}

// ---------------------------------------------------------------------------
extern "C" void kernel_launch(void* const* d_in, const int* in_sizes, int n_in,
                              void* d_out, int out_size)
{
    const float* x      = (const float*)d_in[0];
    const float* w_qkv  = (const float*)d_in[1];
    const float* b_qkv  = (const float*)d_in[2];
    const float* w_proj = (const float*)d_in[3];
    const float* b_proj = (const float*)d_in[4];
    float* out = (float*)d_out;

    __half *xs, *wq, *wph, *wpl, *as;
    cudaGetSymbolAddress((void**)&xs,  g_xs);
    cudaGetSymbolAddress((void**)&wq,  g_wq);
    cudaGetSymbolAddress((void**)&wph, g_wph);
    cudaGetSymbolAddress((void**)&wpl, g_wpl);
    cudaGetSymbolAddress((void**)&as,  g_as);

    // 0) conversions: x, w_qkv -> fp16 single; w_proj -> fp16 hi/lo
    conv_hf<<<(M_ * D_) / 1024, 256>>>(x, xs, M_ * D_);
    conv_hf<<<(D_ * 3 * D_) / 1024, 256>>>(w_qkv, wq, D_ * 3 * D_);
    split_hf<<<(D_ * D_) / 1024, 256>>>(w_proj, wph, wpl, D_ * D_);

    // 1) QKV GEMM (single-term fp16) -> q single (scaled), k single, v hi/lo
    cudaFuncSetAttribute((const void*)gemm_f16<1, 0>,
                         cudaFuncAttributeMaxDynamicSharedMemorySize, 3 * 16384);
    gemm_f16<1, 0><<<dim3(3 * D_ / 128, M_ / 128), 256, 3 * 16384>>>(
        xs, wq, nullptr, b_qkv, nullptr, 3 * D_);

    // 2) tensor-core flash attention (fp16, 2 CTAs/SM)
    cudaFuncSetAttribute((const void*)attn_tc_kernel,
                         cudaFuncAttributeMaxDynamicSharedMemorySize, ATTN_SMEM);
    attn_tc_kernel<<<dim3(T_ / 128, B_ * H_), 256, ATTN_SMEM>>>();

    // 3) proj GEMM (fp16 two-term B — final output keeps full precision)
    cudaFuncSetAttribute((const void*)gemm_f16<0, 1>,
                         cudaFuncAttributeMaxDynamicSharedMemorySize, 3 * 24576);
    gemm_f16<0, 1><<<dim3(D_ / 128, M_ / 128), 256, 3 * 24576>>>(
        as, wph, wpl, b_proj, out, D_);
}

// round 12
// speedup vs baseline: 2.4186x; 1.1913x over previous
#include <cuda_runtime.h>
#include <cuda_fp16.h>
#include <cstdint>

// Problem constants
#define B_  4
#define T_  2048
#define D_  1024
#define H_  16
#define HD_ 64
#define M_  (B_ * T_)        // 8192

// Scratch (device globals — no allocation allowed)
__device__ __half g_qs[B_ * H_ * T_ * HD_];   // q single fp16, pre-scaled SCL2
__device__ __half g_ks[B_ * H_ * T_ * HD_];   // k single fp16
__device__ __half g_vs[B_ * H_ * T_ * HD_];   // v single fp16
__device__ __half g_xs[M_ * D_];              // x single fp16      [M,K]
__device__ __half g_wq[D_ * 3 * D_];          // w_qkv single fp16  [K,N]
__device__ __half g_wph[D_ * D_];             // w_proj fp16 hi/lo  [K,N]
__device__ __half g_wpl[D_ * D_];
__device__ __half g_as[M_ * D_];              // attention out single fp16

// ---------------------------------------------------------------------------
__device__ __forceinline__ uint32_t smem_u32(const void* p) {
    uint32_t a;
    asm("{ .reg .u64 t; cvta.to.shared.u64 t, %1; cvt.u32.u64 %0, t; }"
        : "=r"(a) : "l"(p));
    return a;
}

#define CP_ASYNC16(saddr, gaddr) \
    asm volatile("cp.async.cg.shared.global [%0], [%1], 16;" \
                 :: "r"(saddr), "l"(gaddr))
#define CP_COMMIT()  asm volatile("cp.async.commit_group;")
#define CP_WAIT1()   asm volatile("cp.async.wait_group 1;")
#define CP_WAIT0()   asm volatile("cp.async.wait_group 0;")

#define LDSM_X4(r0, r1, r2, r3, addr) \
    asm volatile("ldmatrix.sync.aligned.m8n8.x4.shared.b16 {%0,%1,%2,%3}, [%4];" \
                 : "=r"(r0), "=r"(r1), "=r"(r2), "=r"(r3) : "r"(addr))
#define LDSM_X4T(r0, r1, r2, r3, addr) \
    asm volatile("ldmatrix.sync.aligned.m8n8.x4.trans.shared.b16 {%0,%1,%2,%3}, [%4];" \
                 : "=r"(r0), "=r"(r1), "=r"(r2), "=r"(r3) : "r"(addr))

#define MMA_F16(c, a, b0, b1) \
    asm volatile("mma.sync.aligned.m16n8k16.row.col.f32.f16.f16.f32 " \
        "{%0,%1,%2,%3}, {%4,%5,%6,%7}, {%8,%9}, {%0,%1,%2,%3};" \
        : "+f"((c)[0]), "+f"((c)[1]), "+f"((c)[2]), "+f"((c)[3]) \
        : "r"((a)[0]), "r"((a)[1]), "r"((a)[2]), "r"((a)[3]), "r"(b0), "r"(b1))

// pack two fp32 -> fp16x2 (lo in low half)
__device__ __forceinline__ uint32_t pack2hf(float lo, float hi) {
    uint32_t r;
    asm("cvt.rn.f16x2.f32 %0, %1, %2;" : "=r"(r) : "f"(hi), "f"(lo));
    return r;
}
__device__ __forceinline__ uint32_t resid2hf(uint32_t h, float lo, float hi) {
    __half2 hh = *reinterpret_cast<__half2*>(&h);
    return pack2hf(lo - __half2float(hh.x), hi - __half2float(hh.y));
}
__device__ __forceinline__ float ex2(float x) {
    float r;
    asm("ex2.approx.f32 %0, %1;" : "=f"(r) : "f"(x));
    return r;
}

// ---------------------------------------------------------------------------
// Prep kernels
// ---------------------------------------------------------------------------
__global__ void split_hf(const float* __restrict__ src,
                         __half* __restrict__ hi, __half* __restrict__ lo, int n)
{
    int i = (blockIdx.x * 256 + threadIdx.x) * 4;
    if (i >= n) return;
    float4 v = *(const float4*)(src + i);
    uint32_t h0 = pack2hf(v.x, v.y), h1 = pack2hf(v.z, v.w);
    uint32_t l0 = resid2hf(h0, v.x, v.y), l1 = resid2hf(h1, v.z, v.w);
    *(uint2*)(hi + i) = make_uint2(h0, h1);
    *(uint2*)(lo + i) = make_uint2(l0, l1);
}

__global__ void conv_hf(const float* __restrict__ src,
                        __half* __restrict__ dst, int n)
{
    int i = (blockIdx.x * 256 + threadIdx.x) * 4;
    if (i >= n) return;
    float4 v = *(const float4*)(src + i);
    *(uint2*)(dst + i) = make_uint2(pack2hf(v.x, v.y), pack2hf(v.z, v.w));
}

// ---------------------------------------------------------------------------
// fp16 GEMM via mma.sync.  BL=1: C = A @ (Bh + Bl); BL=0: C = A @ Bh.
// A single fp16.  8 warps, 64x32 warp tiles (16 warps/SM — proven optimum),
// 3-stage cp.async, 1 sync/chunk.
// EPI=0: plain fp32 store + bias.  EPI=1: QKV scatter (q single pre-scaled,
// k single, v single).
// ---------------------------------------------------------------------------
#define SCL2 0.1803368801111204f   // 0.125 * log2(e)

template <int EPI, int BL>
__global__ __launch_bounds__(256, 2) void gemm_f16(
    const __half* __restrict__ A,
    const __half* __restrict__ Bh16, const __half* __restrict__ Bl16,
    const float* __restrict__ bias, float* __restrict__ C, int N)
{
    constexpr uint32_t STAGE = BL ? 24576 : 16384;
    extern __shared__ char sm[];
    const uint32_t sb = smem_u32(sm);
    const int tid = threadIdx.x;
    const int warp = tid >> 5, lane = tid & 31;
    const int m0 = blockIdx.y * 128, n0 = blockIdx.x * 128;
    const int K = 1024;

    const int a_r0 = (tid * 2) >> 2,     a_c0 = (tid * 2) & 3;
    const int a_r1 = (tid * 2 + 1) >> 2, a_c1 = (tid * 2 + 1) & 3;
    const int b_r0 = (tid * 2) >> 4,     b_c0 = (tid * 2) & 15;
    const int b_r1 = (tid * 2 + 1) >> 4, b_c1 = (tid * 2 + 1) & 15;

    auto load_stage = [&](int c, int buf) {
        const uint32_t st = sb + buf * STAGE;
        CP_ASYNC16(st + a_r0 * 64 + ((a_c0 ^ (a_r0 & 3)) << 4),
                   A + (long)(m0 + a_r0) * K + c * 32 + a_c0 * 8);
        CP_ASYNC16(st + a_r1 * 64 + ((a_c1 ^ (a_r1 & 3)) << 4),
                   A + (long)(m0 + a_r1) * K + c * 32 + a_c1 * 8);
        CP_ASYNC16(st + 8192 + b_r0 * 256 + ((b_c0 ^ (b_r0 & 7)) << 4),
                   Bh16 + (long)(c * 32 + b_r0) * N + n0 + b_c0 * 8);
        CP_ASYNC16(st + 8192 + b_r1 * 256 + ((b_c1 ^ (b_r1 & 7)) << 4),
                   Bh16 + (long)(c * 32 + b_r1) * N + n0 + b_c1 * 8);
        if (BL) {
            CP_ASYNC16(st + 16384 + b_r0 * 256 + ((b_c0 ^ (b_r0 & 7)) << 4),
                       Bl16 + (long)(c * 32 + b_r0) * N + n0 + b_c0 * 8);
            CP_ASYNC16(st + 16384 + b_r1 * 256 + ((b_c1 ^ (b_r1 & 7)) << 4),
                       Bl16 + (long)(c * 32 + b_r1) * N + n0 + b_c1 * 8);
        }
        CP_COMMIT();
    };

    const int wm = (warp & 1) * 64;
    const int wn = (warp >> 1) * 32;

    float acc[4][4][4] = {};

    const int a_lr = lane & 15;
    const int a_lk = lane >> 4;
    const int b_lk = lane & 15;
    const int b_ln = lane >> 4;
    const int nu0 = wn >> 3;

    load_stage(0, 0);
    load_stage(1, 1);

    int buf = 0;                 // c % 3
    for (int c = 0; c < 32; c++) {
        if (c < 31) CP_WAIT1(); else CP_WAIT0();
        __syncthreads();
        if (c + 2 < 32) {
            int nb = buf + 2; if (nb >= 3) nb -= 3;
            load_stage(c + 2, nb);
        }

        const uint32_t st = sb + buf * STAGE;
        #pragma unroll
        for (int ks = 0; ks < 2; ks++) {
            uint32_t ah[4][4];
            #pragma unroll
            for (int mi = 0; mi < 4; mi++) {
                const int row = wm + mi * 16 + a_lr;
                const int ku = ks * 2 + a_lk;
                const uint32_t off = row * 64 + ((ku ^ (row & 3)) << 4);
                LDSM_X4(ah[mi][0], ah[mi][1], ah[mi][2], ah[mi][3], st + off);
            }
            #pragma unroll
            for (int bi = 0; bi < 2; bi++) {
                const int krow = ks * 16 + b_lk;
                const int nu = nu0 + bi * 2 + b_ln;
                const uint32_t boff = krow * 256 + ((nu ^ (krow & 7)) << 4);
                uint32_t bh[4];
                LDSM_X4T(bh[0], bh[1], bh[2], bh[3], st + 8192 + boff);
                #pragma unroll
                for (int mi = 0; mi < 4; mi++) {
                    MMA_F16(acc[mi][bi * 2],     ah[mi], bh[0], bh[1]);
                    MMA_F16(acc[mi][bi * 2 + 1], ah[mi], bh[2], bh[3]);
                }
                if (BL) {
                    uint32_t bl[4];
                    LDSM_X4T(bl[0], bl[1], bl[2], bl[3], st + 16384 + boff);
                    #pragma unroll
                    for (int mi = 0; mi < 4; mi++) {
                        MMA_F16(acc[mi][bi * 2],     ah[mi], bl[0], bl[1]);
                        MMA_F16(acc[mi][bi * 2 + 1], ah[mi], bl[2], bl[3]);
                    }
                }
            }
        }
        if (++buf == 3) buf = 0;
    }

    // Epilogue
    const int tg = lane >> 2, ti = lane & 3;
    #pragma unroll
    for (int mi = 0; mi < 4; mi++) {
        #pragma unroll
        for (int nj = 0; nj < 4; nj++) {
            const int n = n0 + wn + nj * 8 + ti * 2;
            const float bx = __ldg(&bias[n]), by = __ldg(&bias[n + 1]);
            #pragma unroll
            for (int half = 0; half < 2; half++) {
                const int m = m0 + wm + mi * 16 + tg + half * 8;
                float ox = acc[mi][nj][half * 2 + 0] + bx;
                float oy = acc[mi][nj][half * 2 + 1] + by;
                if (EPI == 0) {
                    *(float2*)(C + (long)m * N + n) = make_float2(ox, oy);
                } else {
                    const int bidx = m >> 11, t = m & (T_ - 1);
                    const int which = n >> 10;
                    const int rem = n & 1023;
                    const int h = rem >> 6, hd = rem & 63;
                    long off = (((long)bidx * H_ + h) * T_ + t) * HD_ + hd;
                    if (which == 0) {
                        *(uint32_t*)(g_qs + off) = pack2hf(ox * SCL2, oy * SCL2);
                    } else if (which == 1) {
                        *(uint32_t*)(g_ks + off) = pack2hf(ox, oy);
                    } else {
                        *(uint32_t*)(g_vs + off) = pack2hf(ox, oy);
                    }
                }
            }
        }
    }
}

// ---------------------------------------------------------------------------
// Tensor-core causal flash attention, all single fp16 operands:
// S  = q K   (32 mma/chunk);  PV = P V  (32 mma/chunk)
// smem: Q 16KB + 2 stages x (K 8KB + V 8KB) = 48KB/CTA; 2 CTAs/SM.
// ---------------------------------------------------------------------------
#define ATTN_SMEM (16384 + 2 * 16384)

__global__ __launch_bounds__(256, 2) void attn_tc_kernel()
{
    extern __shared__ char sm[];
    const uint32_t sb = smem_u32(sm);
    const int tid = threadIdx.x;
    const int w = tid >> 5, lane = tid & 31;
    const int tg = lane >> 2, ti = lane & 3;
    const int qt = 15 - blockIdx.x;           // big tiles first
    const int bh = blockIdx.y;
    const int qbase = qt * 128 + w * 16;
    const int r0 = qbase + tg;                // thread rows r0, r0+8

    const long bhoff = (long)bh * T_ * HD_;

    // ---- issue Q loads (rows of 128B, swizzled) + KV tile 0
    {
        const int row = tid >> 1;
        const int u0 = (tid & 1) * 4;
        const long gq = bhoff + (long)(qt * 128 + row) * HD_;
        #pragma unroll
        for (int i = 0; i < 4; i++) {
            const int u = u0 + i;
            CP_ASYNC16(sb + row * 128 + ((u ^ (row & 7)) << 4), g_qs + gq + u * 8);
        }
    }
    // KV producer: 256 threads = 2 parts (K, V) x 64 rows x 2 half-rows
    const int kvp  = tid >> 7;           // 0 = K, 1 = V
    const int kvr  = (tid & 127) >> 1;   // row 0..63
    const int kvh  = tid & 1;            // half-row: 4 x 16B units
    const __half* kvsrc = kvp ? g_vs : g_ks;
    const uint32_t kvdst_off = kvp * 8192 + kvr * 128;

    auto load_kv = [&](int kb, int buf) {
        const uint32_t st = sb + 16384 + buf * 16384;
        const long gs = bhoff + (long)(kb * 64 + kvr) * HD_ + kvh * 32;
        #pragma unroll
        for (int u = 0; u < 4; u++) {
            const int uu = kvh * 4 + u;
            CP_ASYNC16(st + kvdst_off + ((uu ^ (kvr & 7)) << 4), kvsrc + gs + u * 8);
        }
    };
    load_kv(0, 0);
    CP_COMMIT();
    CP_WAIT0();
    __syncthreads();

    // ---- Q fragments (single fp16, pre-scaled)
    uint32_t qh[4][4];
    #pragma unroll
    for (int s = 0; s < 4; s++) {
        const int row = w * 16 + (lane & 15);
        const int ku = s * 2 + (lane >> 4);
        const uint32_t ad = sb + row * 128 + ((ku ^ (row & 7)) << 4);
        LDSM_X4(qh[s][0], qh[s][1], qh[s][2], qh[s][3], ad);
    }

    float oacc[8][4] = {};
    float m2a = -1e30f, m2b = -1e30f;
    float la = 0.f, lb = 0.f;

    const int nt = 2 * qt + 2;
    for (int kb = 0; kb < nt; kb++) {
        if (kb > 0) CP_WAIT0();
        __syncthreads();
        if (kb + 1 < nt) { load_kv(kb + 1, (kb + 1) & 1); CP_COMMIT(); }

        if (kb * 64 > qbase + 15) continue;   // warp fully masked

        const uint32_t stK = sb + 16384 + (kb & 1) * 16384;
        const uint32_t stV = stK + 8192;

        // ---- S = q K   (log2 domain already; both single fp16)
        float sacc[8][4] = {};
        #pragma unroll
        for (int s = 0; s < 4; s++) {
            #pragma unroll
            for (int g = 0; g < 4; g++) {
                const int row = g * 16 + (lane & 15);
                const uint32_t ka = stK + row * 128 +
                    (((s * 2 + (lane >> 4)) ^ (row & 7)) << 4);
                uint32_t h0, h1, h2, h3;
                LDSM_X4(h0, h1, h2, h3, ka);
                MMA_F16(sacc[2 * g],     qh[s], h0, h2);
                MMA_F16(sacc[2 * g + 1], qh[s], h1, h3);
            }
        }

        // ---- causal mask + row max (values already in log2 domain)
        const bool needmask = (kb * 64 + 63) > r0;
        float mra = -1e30f, mrb = -1e30f;
        #pragma unroll
        for (int j = 0; j < 8; j++) {
            const int c0 = kb * 64 + 8 * j + 2 * ti, c1 = c0 + 1;
            float z0 = sacc[j][0];
            float z1 = sacc[j][1];
            float z2 = sacc[j][2];
            float z3 = sacc[j][3];
            if (needmask) {
                if (c0 > r0) z0 = -1e30f;
                if (c1 > r0) z1 = -1e30f;
                if (c0 > r0 + 8) z2 = -1e30f;
                if (c1 > r0 + 8) z3 = -1e30f;
            }
            sacc[j][0] = z0; sacc[j][1] = z1; sacc[j][2] = z2; sacc[j][3] = z3;
            mra = fmaxf(mra, fmaxf(z0, z1));
            mrb = fmaxf(mrb, fmaxf(z2, z3));
        }
        mra = fmaxf(mra, __shfl_xor_sync(0xffffffffu, mra, 1));
        mra = fmaxf(mra, __shfl_xor_sync(0xffffffffu, mra, 2));
        mrb = fmaxf(mrb, __shfl_xor_sync(0xffffffffu, mrb, 1));
        mrb = fmaxf(mrb, __shfl_xor_sync(0xffffffffu, mrb, 2));

        const float mna = fmaxf(m2a, mra);
        const float mnb = fmaxf(m2b, mrb);
        const float alpa = ex2(m2a - mna);
        const float alpb = ex2(m2b - mnb);
        m2a = mna; m2b = mnb;

        #pragma unroll
        for (int j = 0; j < 8; j++) {
            oacc[j][0] *= alpa; oacc[j][1] *= alpa;
            oacc[j][2] *= alpb; oacc[j][3] *= alpb;
        }

        // ---- exp + pack P to single fp16 (A-frag layout)
        uint32_t pha[8], phb[8];
        float sa = 0.f, sbm = 0.f;
        #pragma unroll
        for (int j = 0; j < 8; j++) {
            float p0 = ex2(sacc[j][0] - m2a);
            float p1 = ex2(sacc[j][1] - m2a);
            float p2 = ex2(sacc[j][2] - m2b);
            float p3 = ex2(sacc[j][3] - m2b);
            sa += p0 + p1; sbm += p2 + p3;
            pha[j] = pack2hf(p0, p1);
            phb[j] = pack2hf(p2, p3);
        }
        sa  += __shfl_xor_sync(0xffffffffu, sa, 1);
        sa  += __shfl_xor_sync(0xffffffffu, sa, 2);
        sbm += __shfl_xor_sync(0xffffffffu, sbm, 1);
        sbm += __shfl_xor_sync(0xffffffffu, sbm, 2);
        la = la * alpa + sa;
        lb = lb * alpb + sbm;

        // ---- O += P V  (single fp16 V)
        #pragma unroll
        for (int s = 0; s < 4; s++) {
            uint32_t aH[4] = {pha[2 * s], phb[2 * s], pha[2 * s + 1], phb[2 * s + 1]};
            #pragma unroll
            for (int b = 0; b < 4; b++) {
                const int krow = s * 16 + (lane & 15);
                const uint32_t va = stV + krow * 128 +
                    (((b * 2 + (lane >> 4)) ^ (krow & 7)) << 4);
                uint32_t h0, h1, h2, h3;
                LDSM_X4T(h0, h1, h2, h3, va);
                MMA_F16(oacc[2 * b],     aH, h0, h1);
                MMA_F16(oacc[2 * b + 1], aH, h2, h3);
            }
        }
    }

    // ---- epilogue: normalize, single fp16, write [B,T,H*HD]
    const float inva = 1.0f / la, invb = 1.0f / lb;
    const int bidx = bh >> 4, h = bh & 15;
    const long rowa = ((long)(bidx * T_ + qbase + tg)) * D_ + h * HD_;
    const long rowb = rowa + 8L * D_;
    #pragma unroll
    for (int j = 0; j < 8; j++) {
        const int col = 8 * j + 2 * ti;
        *(uint32_t*)(g_as + rowa + col) = pack2hf(oacc[j][0] * inva, oacc[j][1] * inva);
        *(uint32_t*)(g_as + rowb + col) = pack2hf(oacc[j][2] * invb, oacc[j][3] * invb);
    }
}

// ---------------------------------------------------------------------------
extern "C" void kernel_launch(void* const* d_in, const int* in_sizes, int n_in,
                              void* d_out, int out_size)
{
    const float* x      = (const float*)d_in[0];
    const float* w_qkv  = (const float*)d_in[1];
    const float* b_qkv  = (const float*)d_in[2];
    const float* w_proj = (const float*)d_in[3];
    const float* b_proj = (const float*)d_in[4];
    float* out = (float*)d_out;

    __half *xs, *wq, *wph, *wpl, *as;
    cudaGetSymbolAddress((void**)&xs,  g_xs);
    cudaGetSymbolAddress((void**)&wq,  g_wq);
    cudaGetSymbolAddress((void**)&wph, g_wph);
    cudaGetSymbolAddress((void**)&wpl, g_wpl);
    cudaGetSymbolAddress((void**)&as,  g_as);

    // 0) conversions: x, w_qkv -> fp16 single; w_proj -> fp16 hi/lo
    conv_hf<<<(M_ * D_) / 1024, 256>>>(x, xs, M_ * D_);
    conv_hf<<<(D_ * 3 * D_) / 1024, 256>>>(w_qkv, wq, D_ * 3 * D_);
    split_hf<<<(D_ * D_) / 1024, 256>>>(w_proj, wph, wpl, D_ * D_);

    // 1) QKV GEMM (single-term fp16) -> q single (scaled), k single, v single
    cudaFuncSetAttribute((const void*)gemm_f16<1, 0>,
                         cudaFuncAttributeMaxDynamicSharedMemorySize, 3 * 16384);
    gemm_f16<1, 0><<<dim3(3 * D_ / 128, M_ / 128), 256, 3 * 16384>>>(
        xs, wq, nullptr, b_qkv, nullptr, 3 * D_);

    // 2) tensor-core flash attention (all single fp16, 2 CTAs/SM)
    cudaFuncSetAttribute((const void*)attn_tc_kernel,
                         cudaFuncAttributeMaxDynamicSharedMemorySize, ATTN_SMEM);
    attn_tc_kernel<<<dim3(T_ / 128, B_ * H_), 256, ATTN_SMEM>>>();

    // 3) proj GEMM (fp16 two-term B — final output keeps precision headroom)
    cudaFuncSetAttribute((const void*)gemm_f16<0, 1>,
                         cudaFuncAttributeMaxDynamicSharedMemorySize, 3 * 24576);
    gemm_f16<0, 1><<<dim3(D_ / 128, M_ / 128), 256, 3 * 24576>>>(
        as, wph, wpl, b_proj, out, D_);
}

// round 13
// speedup vs baseline: 2.7064x; 1.1190x over previous
#include <cuda_runtime.h>
#include <cuda_fp16.h>
#include <cstdint>

// Problem constants
#define B_  4
#define T_  2048
#define D_  1024
#define H_  16
#define HD_ 64
#define M_  (B_ * T_)        // 8192

// Scratch (device globals — no allocation allowed)
__device__ __half g_qs[B_ * H_ * T_ * HD_];   // q single fp16, pre-scaled SCL2
__device__ __half g_ks[B_ * H_ * T_ * HD_];   // k single fp16
__device__ __half g_vs[B_ * H_ * T_ * HD_];   // v single fp16
__device__ __half g_xs[M_ * D_];              // x single fp16      [M,K]
__device__ __half g_wq[D_ * 3 * D_];          // w_qkv single fp16  [K,N]
__device__ __half g_wp[D_ * D_];              // w_proj single fp16 [K,N]
__device__ __half g_as[M_ * D_];              // attention out single fp16

// ---------------------------------------------------------------------------
__device__ __forceinline__ uint32_t smem_u32(const void* p) {
    uint32_t a;
    asm("{ .reg .u64 t; cvta.to.shared.u64 t, %1; cvt.u32.u64 %0, t; }"
        : "=r"(a) : "l"(p));
    return a;
}

#define CP_ASYNC16(saddr, gaddr) \
    asm volatile("cp.async.cg.shared.global [%0], [%1], 16;" \
                 :: "r"(saddr), "l"(gaddr))
#define CP_COMMIT()  asm volatile("cp.async.commit_group;")
#define CP_WAIT1()   asm volatile("cp.async.wait_group 1;")
#define CP_WAIT0()   asm volatile("cp.async.wait_group 0;")

#define LDSM_X4(r0, r1, r2, r3, addr) \
    asm volatile("ldmatrix.sync.aligned.m8n8.x4.shared.b16 {%0,%1,%2,%3}, [%4];" \
                 : "=r"(r0), "=r"(r1), "=r"(r2), "=r"(r3) : "r"(addr))
#define LDSM_X4T(r0, r1, r2, r3, addr) \
    asm volatile("ldmatrix.sync.aligned.m8n8.x4.trans.shared.b16 {%0,%1,%2,%3}, [%4];" \
                 : "=r"(r0), "=r"(r1), "=r"(r2), "=r"(r3) : "r"(addr))

#define MMA_F16(c, a, b0, b1) \
    asm volatile("mma.sync.aligned.m16n8k16.row.col.f32.f16.f16.f32 " \
        "{%0,%1,%2,%3}, {%4,%5,%6,%7}, {%8,%9}, {%0,%1,%2,%3};" \
        : "+f"((c)[0]), "+f"((c)[1]), "+f"((c)[2]), "+f"((c)[3]) \
        : "r"((a)[0]), "r"((a)[1]), "r"((a)[2]), "r"((a)[3]), "r"(b0), "r"(b1))

// pack two fp32 -> fp16x2 (lo in low half)
__device__ __forceinline__ uint32_t pack2hf(float lo, float hi) {
    uint32_t r;
    asm("cvt.rn.f16x2.f32 %0, %1, %2;" : "=r"(r) : "f"(hi), "f"(lo));
    return r;
}
__device__ __forceinline__ float ex2(float x) {
    float r;
    asm("ex2.approx.f32 %0, %1;" : "=f"(r) : "f"(x));
    return r;
}

// ---------------------------------------------------------------------------
// Prep: fp32 -> fp16
// ---------------------------------------------------------------------------
__global__ void conv_hf(const float* __restrict__ src,
                        __half* __restrict__ dst, int n)
{
    int i = (blockIdx.x * 256 + threadIdx.x) * 4;
    if (i >= n) return;
    float4 v = *(const float4*)(src + i);
    *(uint2*)(dst + i) = make_uint2(pack2hf(v.x, v.y), pack2hf(v.z, v.w));
}

// ---------------------------------------------------------------------------
// fp16 GEMM via mma.sync, BK=64 chunks (half the barriers of BK=32 — R12
// profile showed tensor 41% / L1 60% / issue 20%: per-chunk serialization,
// not pipe saturation, was binding).
// 8 warps, 64x32 warp tiles (16 warps/SM), 3-stage cp.async, 1 sync/chunk.
// Stage = A(128x64 f16, 16KB) + B(64x128 f16, 16KB) = 32KB.
// EPI=0: fp32 store + bias.  EPI=1: QKV scatter (q pre-scaled, k, v single).
// ---------------------------------------------------------------------------
#define GEMM_SMEM (3 * 32768)
#define SCL2 0.1803368801111204f   // 0.125 * log2(e)

template <int EPI>
__global__ __launch_bounds__(256, 2) void gemm_f16(
    const __half* __restrict__ A, const __half* __restrict__ Bmat,
    const float* __restrict__ bias, float* __restrict__ C, int N)
{
    extern __shared__ char sm[];
    const uint32_t sb = smem_u32(sm);
    const int tid = threadIdx.x;
    const int warp = tid >> 5, lane = tid & 31;
    const int m0 = blockIdx.y * 128, n0 = blockIdx.x * 128;
    const int K = 1024;

    // producer: A rows of 128B (8 units), 2 threads/row; B rows of 256B
    // (16 units), 4 threads/row.
    const int a_row = tid >> 1, a_u0 = (tid & 1) * 4;
    const int b_row = tid >> 2, b_u0 = (tid & 3) * 4;

    auto load_stage = [&](int c, int buf) {
        const uint32_t st = sb + buf * 32768;
        const __half* ag = A + (long)(m0 + a_row) * K + c * 64;
        const __half* bg = Bmat + (long)(c * 64 + b_row) * N + n0;
        #pragma unroll
        for (int i = 0; i < 4; i++) {
            const int au = a_u0 + i, bu = b_u0 + i;
            CP_ASYNC16(st + a_row * 128 + ((au ^ (a_row & 7)) << 4), ag + au * 8);
            CP_ASYNC16(st + 16384 + b_row * 256 + ((bu ^ (b_row & 7)) << 4),
                       bg + bu * 8);
        }
        CP_COMMIT();
    };

    const int wm = (warp & 1) * 64;
    const int wn = (warp >> 1) * 32;

    float acc[4][4][4] = {};

    const int a_lr = lane & 15;
    const int a_lk = lane >> 4;
    const int b_lk = lane & 15;
    const int b_ln = lane >> 4;
    const int nu0 = wn >> 3;

    load_stage(0, 0);
    load_stage(1, 1);

    int buf = 0;                 // c % 3
    for (int c = 0; c < 16; c++) {
        if (c < 15) CP_WAIT1(); else CP_WAIT0();
        __syncthreads();
        if (c + 2 < 16) {
            int nb = buf + 2; if (nb >= 3) nb -= 3;
            load_stage(c + 2, nb);
        }

        const uint32_t st = sb + buf * 32768;
        #pragma unroll
        for (int ks = 0; ks < 4; ks++) {
            uint32_t ah[4][4];
            #pragma unroll
            for (int mi = 0; mi < 4; mi++) {
                const int row = wm + mi * 16 + a_lr;
                const int ku = ks * 2 + a_lk;
                const uint32_t off = row * 128 + ((ku ^ (row & 7)) << 4);
                LDSM_X4(ah[mi][0], ah[mi][1], ah[mi][2], ah[mi][3], st + off);
            }
            #pragma unroll
            for (int bi = 0; bi < 2; bi++) {
                const int krow = ks * 16 + b_lk;
                const int nu = nu0 + bi * 2 + b_ln;
                const uint32_t boff = 16384 + krow * 256 + ((nu ^ (krow & 7)) << 4);
                uint32_t bh[4];
                LDSM_X4T(bh[0], bh[1], bh[2], bh[3], st + boff);
                #pragma unroll
                for (int mi = 0; mi < 4; mi++) {
                    MMA_F16(acc[mi][bi * 2],     ah[mi], bh[0], bh[1]);
                    MMA_F16(acc[mi][bi * 2 + 1], ah[mi], bh[2], bh[3]);
                }
            }
        }
        if (++buf == 3) buf = 0;
    }

    // Epilogue
    const int tg = lane >> 2, ti = lane & 3;
    #pragma unroll
    for (int mi = 0; mi < 4; mi++) {
        #pragma unroll
        for (int nj = 0; nj < 4; nj++) {
            const int n = n0 + wn + nj * 8 + ti * 2;
            const float bx = __ldg(&bias[n]), by = __ldg(&bias[n + 1]);
            #pragma unroll
            for (int half = 0; half < 2; half++) {
                const int m = m0 + wm + mi * 16 + tg + half * 8;
                float ox = acc[mi][nj][half * 2 + 0] + bx;
                float oy = acc[mi][nj][half * 2 + 1] + by;
                if (EPI == 0) {
                    *(float2*)(C + (long)m * N + n) = make_float2(ox, oy);
                } else {
                    const int bidx = m >> 11, t = m & (T_ - 1);
                    const int which = n >> 10;
                    const int rem = n & 1023;
                    const int h = rem >> 6, hd = rem & 63;
                    long off = (((long)bidx * H_ + h) * T_ + t) * HD_ + hd;
                    if (which == 0) {
                        *(uint32_t*)(g_qs + off) = pack2hf(ox * SCL2, oy * SCL2);
                    } else if (which == 1) {
                        *(uint32_t*)(g_ks + off) = pack2hf(ox, oy);
                    } else {
                        *(uint32_t*)(g_vs + off) = pack2hf(ox, oy);
                    }
                }
            }
        }
    }
}

// ---------------------------------------------------------------------------
// Tensor-core causal flash attention, all single fp16 operands (R12, proven):
// S = q K (32 mma/chunk); PV = P V (32 mma/chunk).
// smem: Q 16KB + 2 stages x (K 8KB + V 8KB) = 48KB/CTA; 2 CTAs/SM.
// ---------------------------------------------------------------------------
#define ATTN_SMEM (16384 + 2 * 16384)

__global__ __launch_bounds__(256, 2) void attn_tc_kernel()
{
    extern __shared__ char sm[];
    const uint32_t sb = smem_u32(sm);
    const int tid = threadIdx.x;
    const int w = tid >> 5, lane = tid & 31;
    const int tg = lane >> 2, ti = lane & 3;
    const int qt = 15 - blockIdx.x;           // big tiles first
    const int bh = blockIdx.y;
    const int qbase = qt * 128 + w * 16;
    const int r0 = qbase + tg;                // thread rows r0, r0+8

    const long bhoff = (long)bh * T_ * HD_;

    // ---- issue Q loads (rows of 128B, swizzled) + KV tile 0
    {
        const int row = tid >> 1;
        const int u0 = (tid & 1) * 4;
        const long gq = bhoff + (long)(qt * 128 + row) * HD_;
        #pragma unroll
        for (int i = 0; i < 4; i++) {
            const int u = u0 + i;
            CP_ASYNC16(sb + row * 128 + ((u ^ (row & 7)) << 4), g_qs + gq + u * 8);
        }
    }
    // KV producer: 256 threads = 2 parts (K, V) x 64 rows x 2 half-rows
    const int kvp  = tid >> 7;           // 0 = K, 1 = V
    const int kvr  = (tid & 127) >> 1;   // row 0..63
    const int kvh  = tid & 1;            // half-row: 4 x 16B units
    const __half* kvsrc = kvp ? g_vs : g_ks;
    const uint32_t kvdst_off = kvp * 8192 + kvr * 128;

    auto load_kv = [&](int kb, int buf) {
        const uint32_t st = sb + 16384 + buf * 16384;
        const long gs = bhoff + (long)(kb * 64 + kvr) * HD_ + kvh * 32;
        #pragma unroll
        for (int u = 0; u < 4; u++) {
            const int uu = kvh * 4 + u;
            CP_ASYNC16(st + kvdst_off + ((uu ^ (kvr & 7)) << 4), kvsrc + gs + u * 8);
        }
    };
    load_kv(0, 0);
    CP_COMMIT();
    CP_WAIT0();
    __syncthreads();

    // ---- Q fragments (single fp16, pre-scaled)
    uint32_t qh[4][4];
    #pragma unroll
    for (int s = 0; s < 4; s++) {
        const int row = w * 16 + (lane & 15);
        const int ku = s * 2 + (lane >> 4);
        const uint32_t ad = sb + row * 128 + ((ku ^ (row & 7)) << 4);
        LDSM_X4(qh[s][0], qh[s][1], qh[s][2], qh[s][3], ad);
    }

    float oacc[8][4] = {};
    float m2a = -1e30f, m2b = -1e30f;
    float la = 0.f, lb = 0.f;

    const int nt = 2 * qt + 2;
    for (int kb = 0; kb < nt; kb++) {
        if (kb > 0) CP_WAIT0();
        __syncthreads();
        if (kb + 1 < nt) { load_kv(kb + 1, (kb + 1) & 1); CP_COMMIT(); }

        if (kb * 64 > qbase + 15) continue;   // warp fully masked

        const uint32_t stK = sb + 16384 + (kb & 1) * 16384;
        const uint32_t stV = stK + 8192;

        // ---- S = q K   (log2 domain already; both single fp16)
        float sacc[8][4] = {};
        #pragma unroll
        for (int s = 0; s < 4; s++) {
            #pragma unroll
            for (int g = 0; g < 4; g++) {
                const int row = g * 16 + (lane & 15);
                const uint32_t ka = stK + row * 128 +
                    (((s * 2 + (lane >> 4)) ^ (row & 7)) << 4);
                uint32_t h0, h1, h2, h3;
                LDSM_X4(h0, h1, h2, h3, ka);
                MMA_F16(sacc[2 * g],     qh[s], h0, h2);
                MMA_F16(sacc[2 * g + 1], qh[s], h1, h3);
            }
        }

        // ---- causal mask + row max
        const bool needmask = (kb * 64 + 63) > r0;
        float mra = -1e30f, mrb = -1e30f;
        #pragma unroll
        for (int j = 0; j < 8; j++) {
            const int c0 = kb * 64 + 8 * j + 2 * ti, c1 = c0 + 1;
            float z0 = sacc[j][0];
            float z1 = sacc[j][1];
            float z2 = sacc[j][2];
            float z3 = sacc[j][3];
            if (needmask) {
                if (c0 > r0) z0 = -1e30f;
                if (c1 > r0) z1 = -1e30f;
                if (c0 > r0 + 8) z2 = -1e30f;
                if (c1 > r0 + 8) z3 = -1e30f;
            }
            sacc[j][0] = z0; sacc[j][1] = z1; sacc[j][2] = z2; sacc[j][3] = z3;
            mra = fmaxf(mra, fmaxf(z0, z1));
            mrb = fmaxf(mrb, fmaxf(z2, z3));
        }
        mra = fmaxf(mra, __shfl_xor_sync(0xffffffffu, mra, 1));
        mra = fmaxf(mra, __shfl_xor_sync(0xffffffffu, mra, 2));
        mrb = fmaxf(mrb, __shfl_xor_sync(0xffffffffu, mrb, 1));
        mrb = fmaxf(mrb, __shfl_xor_sync(0xffffffffu, mrb, 2));

        const float mna = fmaxf(m2a, mra);
        const float mnb = fmaxf(m2b, mrb);
        const float alpa = ex2(m2a - mna);
        const float alpb = ex2(m2b - mnb);
        m2a = mna; m2b = mnb;

        #pragma unroll
        for (int j = 0; j < 8; j++) {
            oacc[j][0] *= alpa; oacc[j][1] *= alpa;
            oacc[j][2] *= alpb; oacc[j][3] *= alpb;
        }

        // ---- exp + pack P to single fp16 (A-frag layout)
        uint32_t pha[8], phb[8];
        float sa = 0.f, sbm = 0.f;
        #pragma unroll
        for (int j = 0; j < 8; j++) {
            float p0 = ex2(sacc[j][0] - m2a);
            float p1 = ex2(sacc[j][1] - m2a);
            float p2 = ex2(sacc[j][2] - m2b);
            float p3 = ex2(sacc[j][3] - m2b);
            sa += p0 + p1; sbm += p2 + p3;
            pha[j] = pack2hf(p0, p1);
            phb[j] = pack2hf(p2, p3);
        }
        sa  += __shfl_xor_sync(0xffffffffu, sa, 1);
        sa  += __shfl_xor_sync(0xffffffffu, sa, 2);
        sbm += __shfl_xor_sync(0xffffffffu, sbm, 1);
        sbm += __shfl_xor_sync(0xffffffffu, sbm, 2);
        la = la * alpa + sa;
        lb = lb * alpb + sbm;

        // ---- O += P V
        #pragma unroll
        for (int s = 0; s < 4; s++) {
            uint32_t aH[4] = {pha[2 * s], phb[2 * s], pha[2 * s + 1], phb[2 * s + 1]};
            #pragma unroll
            for (int b = 0; b < 4; b++) {
                const int krow = s * 16 + (lane & 15);
                const uint32_t va = stV + krow * 128 +
                    (((b * 2 + (lane >> 4)) ^ (krow & 7)) << 4);
                uint32_t h0, h1, h2, h3;
                LDSM_X4T(h0, h1, h2, h3, va);
                MMA_F16(oacc[2 * b],     aH, h0, h1);
                MMA_F16(oacc[2 * b + 1], aH, h2, h3);
            }
        }
    }

    // ---- epilogue: normalize, single fp16, write [B,T,H*HD]
    const float inva = 1.0f / la, invb = 1.0f / lb;
    const int bidx = bh >> 4, h = bh & 15;
    const long rowa = ((long)(bidx * T_ + qbase + tg)) * D_ + h * HD_;
    const long rowb = rowa + 8L * D_;
    #pragma unroll
    for (int j = 0; j < 8; j++) {
        const int col = 8 * j + 2 * ti;
        *(uint32_t*)(g_as + rowa + col) = pack2hf(oacc[j][0] * inva, oacc[j][1] * inva);
        *(uint32_t*)(g_as + rowb + col) = pack2hf(oacc[j][2] * invb, oacc[j][3] * invb);
    }
}

// ---------------------------------------------------------------------------
extern "C" void kernel_launch(void* const* d_in, const int* in_sizes, int n_in,
                              void* d_out, int out_size)
{
    const float* x      = (const float*)d_in[0];
    const float* w_qkv  = (const float*)d_in[1];
    const float* b_qkv  = (const float*)d_in[2];
    const float* w_proj = (const float*)d_in[3];
    const float* b_proj = (const float*)d_in[4];
    float* out = (float*)d_out;

    __half *xs, *wq, *wp, *as;
    cudaGetSymbolAddress((void**)&xs, g_xs);
    cudaGetSymbolAddress((void**)&wq, g_wq);
    cudaGetSymbolAddress((void**)&wp, g_wp);
    cudaGetSymbolAddress((void**)&as, g_as);

    // 0) conversions to fp16
    conv_hf<<<(M_ * D_) / 1024, 256>>>(x, xs, M_ * D_);
    conv_hf<<<(D_ * 3 * D_) / 1024, 256>>>(w_qkv, wq, D_ * 3 * D_);
    conv_hf<<<(D_ * D_) / 1024, 256>>>(w_proj, wp, D_ * D_);

    // 1) QKV GEMM (fp16, BK=64) -> q (scaled) / k / v single fp16
    cudaFuncSetAttribute((const void*)gemm_f16<1>,
                         cudaFuncAttributeMaxDynamicSharedMemorySize, GEMM_SMEM);
    gemm_f16<1><<<dim3(3 * D_ / 128, M_ / 128), 256, GEMM_SMEM>>>(
        xs, wq, b_qkv, nullptr, 3 * D_);

    // 2) tensor-core flash attention (all single fp16, 2 CTAs/SM)
    cudaFuncSetAttribute((const void*)attn_tc_kernel,
                         cudaFuncAttributeMaxDynamicSharedMemorySize, ATTN_SMEM);
    attn_tc_kernel<<<dim3(T_ / 128, B_ * H_), 256, ATTN_SMEM>>>();

    // 3) proj GEMM (fp16, BK=64)
    cudaFuncSetAttribute((const void*)gemm_f16<0>,
                         cudaFuncAttributeMaxDynamicSharedMemorySize, GEMM_SMEM);
    gemm_f16<0><<<dim3(D_ / 128, M_ / 128), 256, GEMM_SMEM>>>(
        as, wp, b_proj, out, D_);
}